// round 2
// baseline (speedup 1.0000x reference)
#include <cuda_runtime.h>

#define DD 1024
#define HH 16
#define HDIM 64
#define BB 2
#define SS 2048
#define M_TOT (BB*SS)      // 4096
#define N_QKV (3*DD)       // 3072
#define ATT_SCALE 0.125f   // 1/sqrt(64)

// scratch (allocation-free rule: device globals)
__device__ float g_q[BB*HH*SS*HDIM];   // [B,H,S,HD]
__device__ float g_k[BB*HH*SS*HDIM];
__device__ float g_v[BB*HH*SS*HDIM];
__device__ float g_ao[M_TOT*DD];       // attention output [B*S, D]

// ---------------------------------------------------------------------------
// Tiled GEMM: C[M,N] = A[M,K] * W[K,N] + bias, BM=BN=64, BK=16, 256 threads,
// 4x4 register micro-tile per thread.
// ---------------------------------------------------------------------------
__global__ __launch_bounds__(256) void qkv_gemm_kernel(
    const float* __restrict__ X, const float* __restrict__ W,
    const float* __restrict__ bias)
{
    __shared__ float As[16][65];   // As[k][m] transposed, padded
    __shared__ float Bs[16][64];   // Bs[k][n]

    const int tid = threadIdx.x;
    const int m0 = blockIdx.y * 64, n0 = blockIdx.x * 64;
    const int ty = tid >> 4, tx = tid & 15;
    const int ar = tid >> 2, ac = (tid & 3) * 4;   // A loader: row, col4
    const int br = tid >> 4, bc = (tid & 15) * 4;  // B loader: row, col4

    float acc[4][4] = {};

    for (int k0 = 0; k0 < DD; k0 += 16) {
        float4 av = *(const float4*)(X + (size_t)(m0 + ar) * DD + k0 + ac);
        As[ac + 0][ar] = av.x; As[ac + 1][ar] = av.y;
        As[ac + 2][ar] = av.z; As[ac + 3][ar] = av.w;
        *(float4*)(&Bs[br][bc]) =
            *(const float4*)(W + (size_t)(k0 + br) * N_QKV + n0 + bc);
        __syncthreads();
        #pragma unroll
        for (int k = 0; k < 16; k++) {
            float4 b4 = *(const float4*)(&Bs[k][tx * 4]);
            float a[4];
            #pragma unroll
            for (int i = 0; i < 4; i++) a[i] = As[k][ty * 4 + i];
            #pragma unroll
            for (int i = 0; i < 4; i++) {
                acc[i][0] += a[i] * b4.x;
                acc[i][1] += a[i] * b4.y;
                acc[i][2] += a[i] * b4.z;
                acc[i][3] += a[i] * b4.w;
            }
        }
        __syncthreads();
    }

    // epilogue: scatter into q/k/v [B,H,S,HD]
    #pragma unroll
    for (int i = 0; i < 4; i++) {
        int m = m0 + ty * 4 + i;
        int b = m >> 11, s = m & 2047;
        #pragma unroll
        for (int j = 0; j < 4; j++) {
            int n = n0 + tx * 4 + j;
            float val = acc[i][j] + bias[n];
            int t = n >> 10, dc = n & 1023;
            int h = dc >> 6, d = dc & 63;
            float* dst = (t == 0) ? g_q : ((t == 1) ? g_k : g_v);
            dst[(((size_t)(b * HH + h)) * SS + s) * HDIM + d] = val;
        }
    }
}

__global__ __launch_bounds__(256) void out_gemm_kernel(
    const float* __restrict__ W, const float* __restrict__ bias,
    float* __restrict__ out)
{
    __shared__ float As[16][65];
    __shared__ float Bs[16][64];

    const int tid = threadIdx.x;
    const int m0 = blockIdx.y * 64, n0 = blockIdx.x * 64;
    const int ty = tid >> 4, tx = tid & 15;
    const int ar = tid >> 2, ac = (tid & 3) * 4;
    const int br = tid >> 4, bc = (tid & 15) * 4;

    float acc[4][4] = {};

    for (int k0 = 0; k0 < DD; k0 += 16) {
        float4 av = *(const float4*)(g_ao + (size_t)(m0 + ar) * DD + k0 + ac);
        As[ac + 0][ar] = av.x; As[ac + 1][ar] = av.y;
        As[ac + 2][ar] = av.z; As[ac + 3][ar] = av.w;
        *(float4*)(&Bs[br][bc]) =
            *(const float4*)(W + (size_t)(k0 + br) * DD + n0 + bc);
        __syncthreads();
        #pragma unroll
        for (int k = 0; k < 16; k++) {
            float4 b4 = *(const float4*)(&Bs[k][tx * 4]);
            float a[4];
            #pragma unroll
            for (int i = 0; i < 4; i++) a[i] = As[k][ty * 4 + i];
            #pragma unroll
            for (int i = 0; i < 4; i++) {
                acc[i][0] += a[i] * b4.x;
                acc[i][1] += a[i] * b4.y;
                acc[i][2] += a[i] * b4.z;
                acc[i][3] += a[i] * b4.w;
            }
        }
        __syncthreads();
    }

    #pragma unroll
    for (int i = 0; i < 4; i++) {
        int m = m0 + ty * 4 + i;
        #pragma unroll
        for (int j = 0; j < 4; j++) {
            int n = n0 + tx * 4 + j;
            out[(size_t)m * DD + n] = acc[i][j] + bias[n];
        }
    }
}

// ---------------------------------------------------------------------------
// Flash attention, 64x64 tiles, online softmax.
// grid = (S/64, B*H), 256 threads, dyn smem = 3 * 64*65 floats.
// ---------------------------------------------------------------------------
__global__ __launch_bounds__(256) void attn_kernel()
{
    extern __shared__ float sm[];
    float* Qt = sm;               // Qt[d][r]  [64][65]
    float* KV = sm + 64 * 65;     // Kt[d][c] then Vs[k][d]
    float* Ps = sm + 2 * 64 * 65; // Ps[k][r]

    const int tid = threadIdx.x;
    const int ty = tid >> 4, tx = tid & 15;
    const int bh = blockIdx.y;          // b*H + h
    const int q0 = blockIdx.x * 64;

    const float* Qb = g_q + (size_t)bh * SS * HDIM;
    const float* Kb = g_k + (size_t)bh * SS * HDIM;
    const float* Vb = g_v + (size_t)bh * SS * HDIM;

    // load Q tile transposed: Qt[d][r]
    {
        int r = tid >> 2, c0 = (tid & 3) * 16;
        #pragma unroll
        for (int v = 0; v < 4; v++) {
            float4 q4 = *(const float4*)(Qb + (size_t)(q0 + r) * HDIM + c0 + v * 4);
            Qt[(c0 + v * 4 + 0) * 65 + r] = q4.x;
            Qt[(c0 + v * 4 + 1) * 65 + r] = q4.y;
            Qt[(c0 + v * 4 + 2) * 65 + r] = q4.z;
            Qt[(c0 + v * 4 + 3) * 65 + r] = q4.w;
        }
    }

    float mi[4], li[4], O[4][4] = {};
    #pragma unroll
    for (int i = 0; i < 4; i++) { mi[i] = -1e30f; li[i] = 0.f; }

    for (int kt = 0; kt < SS / 64; kt++) {
        const int k0 = kt * 64;

        __syncthreads();  // prior iter done with KV(V) and Ps
        // load K tile transposed: KV[d][c]
        {
            int c = tid >> 2, d0 = (tid & 3) * 16;
            #pragma unroll
            for (int v = 0; v < 4; v++) {
                float4 k4 = *(const float4*)(Kb + (size_t)(k0 + c) * HDIM + d0 + v * 4);
                KV[(d0 + v * 4 + 0) * 65 + c] = k4.x;
                KV[(d0 + v * 4 + 1) * 65 + c] = k4.y;
                KV[(d0 + v * 4 + 2) * 65 + c] = k4.z;
                KV[(d0 + v * 4 + 3) * 65 + c] = k4.w;
            }
        }
        __syncthreads();

        // scores: s[i][j] = sum_d Qt[d][r] * Kt[d][c]
        float s[4][4] = {};
        #pragma unroll 8
        for (int d = 0; d < HDIM; d++) {
            float a[4], bvals[4];
            #pragma unroll
            for (int i = 0; i < 4; i++) a[i] = Qt[d * 65 + ty * 4 + i];
            #pragma unroll
            for (int j = 0; j < 4; j++) bvals[j] = KV[d * 65 + tx * 4 + j];
            #pragma unroll
            for (int i = 0; i < 4; i++)
                #pragma unroll
                for (int j = 0; j < 4; j++)
                    s[i][j] += a[i] * bvals[j];
        }

        // online softmax per row (16 lanes share a row group via width-16 shfl)
        #pragma unroll
        for (int i = 0; i < 4; i++) {
            float tmax = -1e30f;
            #pragma unroll
            for (int j = 0; j < 4; j++) {
                s[i][j] *= ATT_SCALE;
                tmax = fmaxf(tmax, s[i][j]);
            }
            #pragma unroll
            for (int off = 8; off; off >>= 1)
                tmax = fmaxf(tmax, __shfl_xor_sync(0xffffffffu, tmax, off, 16));
            float mnew = fmaxf(mi[i], tmax);
            float corr = __expf(mi[i] - mnew);
            float rsum = 0.f;
            #pragma unroll
            for (int j = 0; j < 4; j++) {
                float p = __expf(s[i][j] - mnew);
                s[i][j] = p;
                rsum += p;
            }
            #pragma unroll
            for (int off = 8; off; off >>= 1)
                rsum += __shfl_xor_sync(0xffffffffu, rsum, off, 16);
            li[i] = li[i] * corr + rsum;
            mi[i] = mnew;
            #pragma unroll
            for (int j = 0; j < 4; j++) O[i][j] *= corr;
            // stash P transposed: Ps[kcol][row]
            #pragma unroll
            for (int j = 0; j < 4; j++)
                Ps[(tx * 4 + j) * 65 + ty * 4 + i] = s[i][j];
        }

        __syncthreads();  // all reads of Kt done, all Ps writes done
        // load V tile (natural layout): KV[kk][d]
        {
            int kk = tid >> 2, d0 = (tid & 3) * 16;
            #pragma unroll
            for (int v = 0; v < 4; v++) {
                float4 v4 = *(const float4*)(Vb + (size_t)(k0 + kk) * HDIM + d0 + v * 4);
                KV[kk * 65 + d0 + v * 4 + 0] = v4.x;
                KV[kk * 65 + d0 + v * 4 + 1] = v4.y;
                KV[kk * 65 + d0 + v * 4 + 2] = v4.z;
                KV[kk * 65 + d0 + v * 4 + 3] = v4.w;
            }
        }
        __syncthreads();

        // O += P @ V
        #pragma unroll 8
        for (int kk = 0; kk < 64; kk++) {
            float a[4], bvals[4];
            #pragma unroll
            for (int i = 0; i < 4; i++) a[i] = Ps[kk * 65 + ty * 4 + i];
            #pragma unroll
            for (int j = 0; j < 4; j++) bvals[j] = KV[kk * 65 + tx * 4 + j];
            #pragma unroll
            for (int i = 0; i < 4; i++)
                #pragma unroll
                for (int j = 0; j < 4; j++)
                    O[i][j] += a[i] * bvals[j];
        }
    }

    // write normalized output to g_ao [B*S, D] with column offset h*64
    const int b = bh >> 4, h = bh & 15;
    #pragma unroll
    for (int i = 0; i < 4; i++) {
        float inv = 1.0f / li[i];
        int row = q0 + ty * 4 + i;
        #pragma unroll
        for (int j = 0; j < 4; j++)
            g_ao[((size_t)(b * SS + row)) * DD + h * HDIM + tx * 4 + j] = O[i][j] * inv;
    }
}

// ---------------------------------------------------------------------------
extern "C" void kernel_launch(void* const* d_in, const int* in_sizes, int n_in,
                              void* d_out, int out_size)
{
    const float* x     = (const float*)d_in[0];
    const float* W_qkv = (const float*)d_in[1];
    const float* b_qkv = (const float*)d_in[2];
    const float* W_out = (const float*)d_in[3];
    const float* b_out = (const float*)d_in[4];
    float* out = (float*)d_out;

    // 1) QKV projection + scatter
    qkv_gemm_kernel<<<dim3(N_QKV / 64, M_TOT / 64), 256>>>(x, W_qkv, b_qkv);

    // 2) attention
    const int smem_bytes = 3 * 64 * 65 * (int)sizeof(float);  // 49920
    cudaFuncSetAttribute(attn_kernel,
                         cudaFuncAttributeMaxDynamicSharedMemorySize, smem_bytes);
    attn_kernel<<<dim3(SS / 64, BB * HH), 256, smem_bytes>>>();

    // 3) output projection
    out_gemm_kernel<<<dim3(DD / 64, M_TOT / 64), 256>>>(W_out, b_out, out);
}

// round 5
// speedup vs baseline: 1.2323x; 1.2323x over previous
#include <cuda_runtime.h>

#define DD 1024
#define HH 16
#define HDIM 64
#define BB 2
#define SS 2048
#define M_TOT (BB*SS)      // 4096
#define N_QKV (3*DD)       // 3072
#define ATT_SCALE 0.125f   // 1/sqrt(64)

// scratch (allocation-free rule: device globals)
__device__ float g_q[BB*HH*SS*HDIM];   // [B,H,S,HD]
__device__ float g_k[BB*HH*SS*HDIM];
__device__ float g_v[BB*HH*SS*HDIM];
__device__ float g_ao[(size_t)M_TOT*DD];  // attention output [B*S, D]

// ---------------------------------------------------------------------------
// 128x128x8 double-buffered GEMM, 256 threads, 8x8 register micro-tile.
// C[M,N] = A[M,DD] * W[DD,N] + bias. QKV=true scatters into g_q/g_k/g_v.
// ---------------------------------------------------------------------------
template<int N, bool QKV>
__global__ __launch_bounds__(256)
void gemm128_kernel(const float* __restrict__ A,
                    const float* __restrict__ W,
                    const float* __restrict__ bias,
                    float* __restrict__ C)
{
    __shared__ float As[2][8 * 132];   // As[k][m] transposed, padded
    __shared__ float Bs[2][8 * 128];   // Bs[k][n]

    const int tid = threadIdx.x;
    const int m0 = blockIdx.y * 128, n0 = blockIdx.x * 128;
    const int ty = tid >> 4, tx = tid & 15;
    const int a_r = tid >> 1, a_c = (tid & 1) * 4;   // A loader
    const int b_r = tid >> 5, b_c = (tid & 31) * 4;  // B loader

    const float* Ab = QKV ? A : (const float*)g_ao;
    const float* Aptr = Ab + (size_t)(m0 + a_r) * DD + a_c;
    const float* Wptr = W + (size_t)b_r * N + n0 + b_c;

    float acc[8][8] = {};

    // prologue: tile 0 -> buf 0
    float4 ra = *(const float4*)Aptr;
    float4 rb = *(const float4*)Wptr;
    As[0][(a_c + 0) * 132 + a_r] = ra.x;
    As[0][(a_c + 1) * 132 + a_r] = ra.y;
    As[0][(a_c + 2) * 132 + a_r] = ra.z;
    As[0][(a_c + 3) * 132 + a_r] = ra.w;
    *(float4*)&Bs[0][b_r * 128 + b_c] = rb;
    __syncthreads();

    const int KT = DD / 8;  // 128
    for (int t = 0; t < KT; t++) {
        const int buf = t & 1;
        if (t + 1 < KT) {
            ra = *(const float4*)(Aptr + (t + 1) * 8);
            rb = *(const float4*)(Wptr + (size_t)(t + 1) * 8 * N);
        }
        const float* as = As[buf];
        const float* bs = Bs[buf];
        #pragma unroll
        for (int k = 0; k < 8; k++) {
            float a[8], b[8];
            *(float4*)(a)     = *(const float4*)&as[k * 132 + ty * 8];
            *(float4*)(a + 4) = *(const float4*)&as[k * 132 + ty * 8 + 4];
            *(float4*)(b)     = *(const float4*)&bs[k * 128 + tx * 8];
            *(float4*)(b + 4) = *(const float4*)&bs[k * 128 + tx * 8 + 4];
            #pragma unroll
            for (int i = 0; i < 8; i++)
                #pragma unroll
                for (int j = 0; j < 8; j++)
                    acc[i][j] += a[i] * b[j];
        }
        if (t + 1 < KT) {
            const int nb = buf ^ 1;
            As[nb][(a_c + 0) * 132 + a_r] = ra.x;
            As[nb][(a_c + 1) * 132 + a_r] = ra.y;
            As[nb][(a_c + 2) * 132 + a_r] = ra.z;
            As[nb][(a_c + 3) * 132 + a_r] = ra.w;
            *(float4*)&Bs[nb][b_r * 128 + b_c] = rb;
            __syncthreads();
        }
    }

    const int n = n0 + tx * 8;
    float bs8[8];
    *(float4*)(bs8)     = *(const float4*)(bias + n);
    *(float4*)(bs8 + 4) = *(const float4*)(bias + n + 4);

    if (QKV) {
        // n..n+7 stays inside one (q|k|v, head) 64-block: n0 mult of 128, tx*8+7 < 64 band
        const int tsel = n >> 10;
        const int dc = n & 1023;
        const int h = dc >> 6, dbase = dc & 63;
        float* dst = (tsel == 0) ? g_q : ((tsel == 1) ? g_k : g_v);
        #pragma unroll
        for (int i = 0; i < 8; i++) {
            const int m = m0 + ty * 8 + i;
            const int b = m >> 11, s = m & 2047;
            float* p = dst + (((size_t)(b * HH + h)) * SS + s) * HDIM + dbase;
            float4 v0 = make_float4(acc[i][0] + bs8[0], acc[i][1] + bs8[1],
                                    acc[i][2] + bs8[2], acc[i][3] + bs8[3]);
            float4 v1 = make_float4(acc[i][4] + bs8[4], acc[i][5] + bs8[5],
                                    acc[i][6] + bs8[6], acc[i][7] + bs8[7]);
            *(float4*)(p)     = v0;
            *(float4*)(p + 4) = v1;
        }
    } else {
        #pragma unroll
        for (int i = 0; i < 8; i++) {
            const int m = m0 + ty * 8 + i;
            float* p = C + (size_t)m * DD + n;
            float4 v0 = make_float4(acc[i][0] + bs8[0], acc[i][1] + bs8[1],
                                    acc[i][2] + bs8[2], acc[i][3] + bs8[3]);
            float4 v1 = make_float4(acc[i][4] + bs8[4], acc[i][5] + bs8[5],
                                    acc[i][6] + bs8[6], acc[i][7] + bs8[7]);
            *(float4*)(p)     = v0;
            *(float4*)(p + 4) = v1;
        }
    }
}

// ---------------------------------------------------------------------------
// Flash attention: 128-query x 64-key tiles, 256 threads (16x16),
// 8x4 micro-tiles for S and O, all-float4 smem access, online softmax.
// dyn smem = Qt[64][132] + Ps[64][132] + KV[64][68]
// ---------------------------------------------------------------------------
__global__ __launch_bounds__(256)
void attn_kernel()
{
    extern __shared__ float sm[];
    float* Qt = sm;                  // Qt[d][r]  d<64, r<128, stride 132
    float* Ps = sm + 64 * 132;       // Ps[k][r]  k<64, r<128, stride 132
    float* KV = sm + 2 * 64 * 132;   // Kt[d][c] (stride 68) then Vs[k][d]

    const int tid = threadIdx.x;
    const int ty = tid >> 4, tx = tid & 15;
    const int bh = blockIdx.y;             // b*H + h
    const int q0 = blockIdx.x * 128;

    const float* Qb = g_q + (size_t)bh * SS * HDIM;
    const float* Kb = g_k + (size_t)bh * SS * HDIM;
    const float* Vb = g_v + (size_t)bh * SS * HDIM;

    const int lr = tid >> 4;          // loader: row within 16-row group
    const int lc = (tid & 15) * 4;    // loader: 4-float column

    // load Q tile transposed (coalesced: 16 lanes cover one 64-float row)
    #pragma unroll
    for (int rr = 0; rr < 128; rr += 16) {
        float4 q4 = *(const float4*)(Qb + (size_t)(q0 + rr + lr) * HDIM + lc);
        Qt[(lc + 0) * 132 + rr + lr] = q4.x;
        Qt[(lc + 1) * 132 + rr + lr] = q4.y;
        Qt[(lc + 2) * 132 + rr + lr] = q4.z;
        Qt[(lc + 3) * 132 + rr + lr] = q4.w;
    }

    float mi[8], li[8], O[8][4];
    #pragma unroll
    for (int i = 0; i < 8; i++) {
        mi[i] = -1e30f; li[i] = 0.f;
        O[i][0] = O[i][1] = O[i][2] = O[i][3] = 0.f;
    }

    for (int kt = 0; kt < SS / 64; kt++) {
        const int k0 = kt * 64;

        __syncthreads();  // prior iter done with KV(V), Ps; first iter: Q stores done
        // load K tile transposed: KV[d][c]
        #pragma unroll
        for (int rr = 0; rr < 64; rr += 16) {
            float4 k4 = *(const float4*)(Kb + (size_t)(k0 + rr + lr) * HDIM + lc);
            KV[(lc + 0) * 68 + rr + lr] = k4.x;
            KV[(lc + 1) * 68 + rr + lr] = k4.y;
            KV[(lc + 2) * 68 + rr + lr] = k4.z;
            KV[(lc + 3) * 68 + rr + lr] = k4.w;
        }
        __syncthreads();

        // S = Q K^T : s[i][j], rows ty*8+i, keys tx*4+j
        float s[8][4] = {};
        #pragma unroll 4
        for (int d = 0; d < HDIM; d++) {
            float a[8], b[4];
            *(float4*)(a)     = *(const float4*)&Qt[d * 132 + ty * 8];
            *(float4*)(a + 4) = *(const float4*)&Qt[d * 132 + ty * 8 + 4];
            *(float4*)(b)     = *(const float4*)&KV[d * 68 + tx * 4];
            #pragma unroll
            for (int i = 0; i < 8; i++)
                #pragma unroll
                for (int j = 0; j < 4; j++)
                    s[i][j] += a[i] * b[j];
        }

        // online softmax (row group = 16 tx lanes, width-16 shfl)
        #pragma unroll
        for (int i = 0; i < 8; i++) {
            float tmax = fmaxf(fmaxf(s[i][0], s[i][1]), fmaxf(s[i][2], s[i][3]));
            #pragma unroll
            for (int off = 8; off; off >>= 1)
                tmax = fmaxf(tmax, __shfl_xor_sync(0xffffffffu, tmax, off, 16));
            tmax *= ATT_SCALE;
            const float mnew = fmaxf(mi[i], tmax);
            const float corr = __expf(mi[i] - mnew);
            float rsum = 0.f;
            #pragma unroll
            for (int j = 0; j < 4; j++) {
                float p = __expf(s[i][j] * ATT_SCALE - mnew);
                s[i][j] = p;
                rsum += p;
            }
            #pragma unroll
            for (int off = 8; off; off >>= 1)
                rsum += __shfl_xor_sync(0xffffffffu, rsum, off, 16);
            li[i] = li[i] * corr + rsum;
            mi[i] = mnew;
            O[i][0] *= corr; O[i][1] *= corr; O[i][2] *= corr; O[i][3] *= corr;
        }

        // stash P transposed: Ps[kcol][row] (float4 along rows)
        #pragma unroll
        for (int j = 0; j < 4; j++) {
            float4 p0 = make_float4(s[0][j], s[1][j], s[2][j], s[3][j]);
            float4 p1 = make_float4(s[4][j], s[5][j], s[6][j], s[7][j]);
            *(float4*)&Ps[(tx * 4 + j) * 132 + ty * 8]     = p0;
            *(float4*)&Ps[(tx * 4 + j) * 132 + ty * 8 + 4] = p1;
        }

        __syncthreads();  // K reads done, Ps writes done
        // load V tile natural: KV[k][d]
        #pragma unroll
        for (int rr = 0; rr < 64; rr += 16) {
            float4 v4 = *(const float4*)(Vb + (size_t)(k0 + rr + lr) * HDIM + lc);
            *(float4*)&KV[(rr + lr) * 68 + lc] = v4;
        }
        __syncthreads();

        // O += P @ V : O[i][j], rows ty*8+i, dims tx*4+j
        #pragma unroll 4
        for (int k = 0; k < 64; k++) {
            float a[8], b[4];
            *(float4*)(a)     = *(const float4*)&Ps[k * 132 + ty * 8];
            *(float4*)(a + 4) = *(const float4*)&Ps[k * 132 + ty * 8 + 4];
            *(float4*)(b)     = *(const float4*)&KV[k * 68 + tx * 4];
            #pragma unroll
            for (int i = 0; i < 8; i++)
                #pragma unroll
                for (int j = 0; j < 4; j++)
                    O[i][j] += a[i] * b[j];
        }
    }

    // normalized write to g_ao [B*S, D], column offset h*64
    const int b = bh >> 4, h = bh & 15;
    #pragma unroll
    for (int i = 0; i < 8; i++) {
        const float inv = 1.0f / li[i];
        const int row = q0 + ty * 8 + i;
        float4 o = make_float4(O[i][0] * inv, O[i][1] * inv,
                               O[i][2] * inv, O[i][3] * inv);
        *(float4*)&g_ao[((size_t)(b * SS + row)) * DD + h * HDIM + tx * 4] = o;
    }
}

// ---------------------------------------------------------------------------
extern "C" void kernel_launch(void* const* d_in, const int* in_sizes, int n_in,
                              void* d_out, int out_size)
{
    const float* x     = (const float*)d_in[0];
    const float* W_qkv = (const float*)d_in[1];
    const float* b_qkv = (const float*)d_in[2];
    const float* W_out = (const float*)d_in[3];
    const float* b_out = (const float*)d_in[4];
    float* out = (float*)d_out;

    // 1) QKV projection + scatter into [B,H,S,HD]
    gemm128_kernel<N_QKV, true>
        <<<dim3(N_QKV / 128, M_TOT / 128), 256>>>(x, W_qkv, b_qkv, nullptr);

    // 2) flash attention
    const int smem_bytes = (2 * 64 * 132 + 64 * 68) * (int)sizeof(float);  // 84992
    cudaFuncSetAttribute(attn_kernel,
                         cudaFuncAttributeMaxDynamicSharedMemorySize, smem_bytes);
    attn_kernel<<<dim3(SS / 128, BB * HH), 256, smem_bytes>>>();

    // 3) output projection
    gemm128_kernel<DD, false>
        <<<dim3(DD / 128, M_TOT / 128), 256>>>(nullptr, W_out, b_out, out);
}

// round 7
// speedup vs baseline: 1.7715x; 1.4376x over previous
#include <cuda_runtime.h>
#include <cuda_bf16.h>
#include <cstdint>

#define DD 1024
#define HH 16
#define HDIM 64
#define BB 2
#define SS 2048
#define M_TOT (BB*SS)      // 4096
#define N_QKV (3*DD)       // 3072
#define ATT_SCALE 0.125f   // 1/sqrt(64)

// ---------------------------------------------------------------------------
// scratch (allocation-free rule: device globals)
// ---------------------------------------------------------------------------
__device__ float g_q[BB*HH*SS*HDIM];   // [B,H,S,HD] fp32
__device__ float g_k[BB*HH*SS*HDIM];
__device__ float g_v[BB*HH*SS*HDIM];
__device__ float g_ao[(size_t)M_TOT*DD];

__device__ __align__(256) __nv_bfloat16 g_xh[(size_t)M_TOT*DD];
__device__ __align__(256) __nv_bfloat16 g_xl[(size_t)M_TOT*DD];
__device__ __align__(256) __nv_bfloat16 g_wqkvh[(size_t)N_QKV*DD];  // W^T [N][K]
__device__ __align__(256) __nv_bfloat16 g_wqkvl[(size_t)N_QKV*DD];
__device__ __align__(256) __nv_bfloat16 g_wouth[(size_t)DD*DD];
__device__ __align__(256) __nv_bfloat16 g_woutl[(size_t)DD*DD];
__device__ __align__(256) __nv_bfloat16 g_aoh[(size_t)M_TOT*DD];
__device__ __align__(256) __nv_bfloat16 g_aol[(size_t)M_TOT*DD];

// ---------------------------------------------------------------------------
// PTX helpers (cp.async / ldmatrix / mma.sync — all base sm_80/90 ISA,
// no sm_103a-only features: the harness lowers through compute_103)
// ---------------------------------------------------------------------------
__device__ __forceinline__ uint32_t smem_to_u32(const void* p) {
    uint32_t a;
    asm("{ .reg .u64 t; cvta.to.shared.u64 t, %1; cvt.u32.u64 %0, t; }"
        : "=r"(a) : "l"(p));
    return a;
}
#define CP_ASYNC16(sm, gp) \
    asm volatile("cp.async.cg.shared.global [%0], [%1], 16;" :: "r"(sm), "l"(gp) : "memory")
#define CP_COMMIT() asm volatile("cp.async.commit_group;" ::: "memory")
#define CP_WAIT1()  asm volatile("cp.async.wait_group 1;" ::: "memory")
#define CP_WAIT0()  asm volatile("cp.async.wait_group 0;" ::: "memory")

#define SWZ128(o) ((o) ^ (((o) >> 3) & 0x70))

__device__ __forceinline__ void ldsm_x4(uint32_t& r0, uint32_t& r1,
                                        uint32_t& r2, uint32_t& r3, uint32_t a) {
    asm volatile("ldmatrix.sync.aligned.m8n8.x4.shared.b16 {%0,%1,%2,%3}, [%4];"
                 : "=r"(r0), "=r"(r1), "=r"(r2), "=r"(r3) : "r"(a));
}
__device__ __forceinline__ void mma16816(float* c, const uint32_t* a,
                                         const uint32_t* b) {
    asm volatile(
        "mma.sync.aligned.m16n8k16.row.col.f32.bf16.bf16.f32 "
        "{%0,%1,%2,%3}, {%4,%5,%6,%7}, {%8,%9}, {%0,%1,%2,%3};"
        : "+f"(c[0]), "+f"(c[1]), "+f"(c[2]), "+f"(c[3])
        : "r"(a[0]), "r"(a[1]), "r"(a[2]), "r"(a[3]), "r"(b[0]), "r"(b[1]));
}

// ---------------------------------------------------------------------------
// split / transpose prep kernels
// ---------------------------------------------------------------------------
__global__ __launch_bounds__(256) void split_kernel(
    const float4* __restrict__ in, uint2* __restrict__ hi, uint2* __restrict__ lo)
{
    int i = blockIdx.x * blockDim.x + threadIdx.x;
    float4 v = in[i];
    float vv[4] = {v.x, v.y, v.z, v.w};
    __nv_bfloat16 h[4], l[4];
    #pragma unroll
    for (int j = 0; j < 4; j++) {
        h[j] = __float2bfloat16(vv[j]);
        l[j] = __float2bfloat16(vv[j] - __bfloat162float(h[j]));
    }
    hi[i] = *(uint2*)h;
    lo[i] = *(uint2*)l;
}

// W[K][N] fp32 -> Wt_hi/lo [N][K=1024] bf16
__global__ __launch_bounds__(256) void transpose_split_kernel(
    const float* __restrict__ W, __nv_bfloat16* __restrict__ Th,
    __nv_bfloat16* __restrict__ Tl, int N)
{
    __shared__ float t[32][33];
    const int k0 = blockIdx.y * 32, n0 = blockIdx.x * 32;
    const int tx = threadIdx.x & 31, ty = threadIdx.x >> 5;
    #pragma unroll
    for (int j = 0; j < 4; j++)
        t[ty + j * 8][tx] = W[(size_t)(k0 + ty + j * 8) * N + n0 + tx];
    __syncthreads();
    #pragma unroll
    for (int j = 0; j < 4; j++) {
        const int n = n0 + ty + j * 8;
        float v = t[tx][ty + j * 8];
        __nv_bfloat16 h = __float2bfloat16(v);
        __nv_bfloat16 l = __float2bfloat16(v - __bfloat162float(h));
        Th[(size_t)n * DD + k0 + tx] = h;
        Tl[(size_t)n * DD + k0 + tx] = l;
    }
}

// ---------------------------------------------------------------------------
// mma.sync split-bf16 GEMM: C[M,N] = A[M,1024] @ W[1024,N] + bias
// A as Ah/Al [M][1024] bf16 (row/K-major), W as transposed Bh/Bl [N][1024].
// 128x128 CTA tile, 8 warps (2x4 -> 64x32 each), K chunks of 64, SW128 smem,
// 2-stage cp.async pipeline. 3 products (hh, hl, lh) into fp32 accumulators.
// ---------------------------------------------------------------------------
template<bool QKV>
__global__ __launch_bounds__(256)
void mma_gemm(const __nv_bfloat16* __restrict__ Ah,
              const __nv_bfloat16* __restrict__ Al,
              const __nv_bfloat16* __restrict__ Bh,
              const __nv_bfloat16* __restrict__ Bl,
              const float* __restrict__ bias,
              float* __restrict__ C)
{
    extern __shared__ char smem[];
    const uint32_t sm0 = smem_to_u32(smem);   // stage s: +s*65536, tile t: +t*16384

    const int tid = threadIdx.x;
    const int wid = tid >> 5, lane = tid & 31;
    const int m0 = blockIdx.y * 128, n0 = blockIdx.x * 128;
    const int wm = wid & 1;          // 0..1 -> 64 rows each
    const int wn = wid >> 1;         // 0..3 -> 32 cols each

    const char* srcs[4] = {
        (const char*)(Ah + (size_t)m0 * DD),
        (const char*)(Al + (size_t)m0 * DD),
        (const char*)(Bh + (size_t)n0 * DD),
        (const char*)(Bl + (size_t)n0 * DD)
    };

    auto load_stage = [&](int stage, int chunk) {
        const uint32_t sbase = sm0 + stage * 65536;
        const size_t coff = (size_t)chunk * 128;  // 64 bf16 = 128 bytes
        #pragma unroll
        for (int t = 0; t < 4; t++) {
            const uint32_t tb = sbase + t * 16384;
            #pragma unroll
            for (int j = 0; j < 4; j++) {
                const int g = tid + j * 256;          // 1024 granules of 16B
                const int r = g >> 3;
                const uint32_t cb = (uint32_t)((g & 7) * 16);
                const uint32_t so = tb + SWZ128((uint32_t)(r * 128) + cb);
                const char* gp = srcs[t] + (size_t)r * (DD * 2) + coff + cb;
                CP_ASYNC16(so, gp);
            }
        }
        CP_COMMIT();
    };

    load_stage(0, 0);
    load_stage(1, 1);

    float acc[4][4][4] = {};   // [mtile][ntile][c0..c3]

    // ldmatrix lane-address components
    const int sub   = lane >> 3;               // 8-lane group 0..3
    const int a_rin = (lane & 7) + (sub & 1) * 8;   // A: row-in-mtile
    const int a_kh  = sub >> 1;                     // A: k16 half
    const int b_nt  = sub >> 1;                     // B: ntile within pair
    const int b_kh  = sub & 1;                      // B: k16 half
    const int b_row = lane & 7;

    const int K_CHUNKS = DD / 64;  // 16
    for (int i = 0; i < K_CHUNKS; i++) {
        const int stage = i & 1;
        if (i + 1 < K_CHUNKS) { CP_WAIT1(); } else { CP_WAIT0(); }
        __syncthreads();

        const uint32_t sb  = sm0 + stage * 65536;
        const uint32_t Ahb = sb, Alb = sb + 16384, Bhb = sb + 32768, Blb = sb + 49152;

        #pragma unroll
        for (int ks = 0; ks < 4; ks++) {
            uint32_t ahf[4][4], alf[4][4], bhf[4][2], blf[4][2];
            const uint32_t gka = (uint32_t)((ks * 2 + a_kh) * 16);
            #pragma unroll
            for (int mt = 0; mt < 4; mt++) {
                const uint32_t off =
                    SWZ128((uint32_t)((wm * 64 + mt * 16 + a_rin) * 128) + gka);
                ldsm_x4(ahf[mt][0], ahf[mt][1], ahf[mt][2], ahf[mt][3], Ahb + off);
                ldsm_x4(alf[mt][0], alf[mt][1], alf[mt][2], alf[mt][3], Alb + off);
            }
            const uint32_t gkb = (uint32_t)((ks * 2 + b_kh) * 16);
            #pragma unroll
            for (int pr = 0; pr < 2; pr++) {
                const uint32_t off =
                    SWZ128((uint32_t)((wn * 32 + pr * 16 + b_nt * 8 + b_row) * 128) + gkb);
                uint32_t r0, r1, r2, r3;
                ldsm_x4(r0, r1, r2, r3, Bhb + off);
                bhf[pr * 2][0] = r0; bhf[pr * 2][1] = r1;
                bhf[pr * 2 + 1][0] = r2; bhf[pr * 2 + 1][1] = r3;
                ldsm_x4(r0, r1, r2, r3, Blb + off);
                blf[pr * 2][0] = r0; blf[pr * 2][1] = r1;
                blf[pr * 2 + 1][0] = r2; blf[pr * 2 + 1][1] = r3;
            }
            #pragma unroll
            for (int mt = 0; mt < 4; mt++)
                #pragma unroll
                for (int nt = 0; nt < 4; nt++) {
                    mma16816(acc[mt][nt], ahf[mt], bhf[nt]);
                    mma16816(acc[mt][nt], ahf[mt], blf[nt]);
                    mma16816(acc[mt][nt], alf[mt], bhf[nt]);
                }
        }
        __syncthreads();
        if (i + 2 < K_CHUNKS) load_stage(stage, i + 2);
    }

    // epilogue: C fragment (cg = lane>>2 row, ctg = lane&3 col-pair)
    const int cg = lane >> 2, ctg = lane & 3;
    const int nb = n0 + wn * 32;

    if (QKV) {
        const int tsel = nb >> 10;
        const int h = (nb & 1023) >> 6;
        const int db = nb & 63;
        float* base = (tsel == 0) ? g_q : (tsel == 1) ? g_k : g_v;
        #pragma unroll
        for (int mt = 0; mt < 4; mt++) {
            const int ma = m0 + wm * 64 + mt * 16 + cg;
            const int mb = ma + 8;
            const int ba = ma >> 11, sa = ma & 2047;
            const int bb = mb >> 11, sbb = mb & 2047;
            float* pa = base + (((size_t)(ba * HH + h)) * SS + sa) * HDIM + db;
            float* pb = base + (((size_t)(bb * HH + h)) * SS + sbb) * HDIM + db;
            #pragma unroll
            for (int nt = 0; nt < 4; nt++) {
                const int cc = nt * 8 + ctg * 2;
                float2 bv = *(const float2*)(bias + nb + cc);
                float2 v0 = make_float2(acc[mt][nt][0] + bv.x, acc[mt][nt][1] + bv.y);
                float2 v1 = make_float2(acc[mt][nt][2] + bv.x, acc[mt][nt][3] + bv.y);
                *(float2*)(pa + cc) = v0;
                *(float2*)(pb + cc) = v1;
            }
        }
    } else {
        #pragma unroll
        for (int mt = 0; mt < 4; mt++) {
            const int ma = m0 + wm * 64 + mt * 16 + cg;
            float* pa = C + (size_t)ma * DD + nb;
            float* pb = C + (size_t)(ma + 8) * DD + nb;
            #pragma unroll
            for (int nt = 0; nt < 4; nt++) {
                const int cc = nt * 8 + ctg * 2;
                float2 bv = *(const float2*)(bias + nb + cc);
                float2 v0 = make_float2(acc[mt][nt][0] + bv.x, acc[mt][nt][1] + bv.y);
                float2 v1 = make_float2(acc[mt][nt][2] + bv.x, acc[mt][nt][3] + bv.y);
                *(float2*)(pa + cc) = v0;
                *(float2*)(pb + cc) = v1;
            }
        }
    }
}

// ---------------------------------------------------------------------------
// Flash attention (proven fp32 SIMT version): 128x64 tiles, 8x4 micro-tiles.
// ---------------------------------------------------------------------------
__global__ __launch_bounds__(256)
void attn_kernel()
{
    extern __shared__ float sm[];
    float* Qt = sm;
    float* Ps = sm + 64 * 132;
    float* KV = sm + 2 * 64 * 132;

    const int tid = threadIdx.x;
    const int ty = tid >> 4, tx = tid & 15;
    const int bh = blockIdx.y;
    const int q0 = blockIdx.x * 128;

    const float* Qb = g_q + (size_t)bh * SS * HDIM;
    const float* Kb = g_k + (size_t)bh * SS * HDIM;
    const float* Vb = g_v + (size_t)bh * SS * HDIM;

    const int lr = tid >> 4;
    const int lc = (tid & 15) * 4;

    #pragma unroll
    for (int rr = 0; rr < 128; rr += 16) {
        float4 q4 = *(const float4*)(Qb + (size_t)(q0 + rr + lr) * HDIM + lc);
        Qt[(lc + 0) * 132 + rr + lr] = q4.x;
        Qt[(lc + 1) * 132 + rr + lr] = q4.y;
        Qt[(lc + 2) * 132 + rr + lr] = q4.z;
        Qt[(lc + 3) * 132 + rr + lr] = q4.w;
    }

    float mi[8], li[8], O[8][4];
    #pragma unroll
    for (int i = 0; i < 8; i++) {
        mi[i] = -1e30f; li[i] = 0.f;
        O[i][0] = O[i][1] = O[i][2] = O[i][3] = 0.f;
    }

    for (int kt = 0; kt < SS / 64; kt++) {
        const int k0 = kt * 64;

        __syncthreads();
        #pragma unroll
        for (int rr = 0; rr < 64; rr += 16) {
            float4 k4 = *(const float4*)(Kb + (size_t)(k0 + rr + lr) * HDIM + lc);
            KV[(lc + 0) * 68 + rr + lr] = k4.x;
            KV[(lc + 1) * 68 + rr + lr] = k4.y;
            KV[(lc + 2) * 68 + rr + lr] = k4.z;
            KV[(lc + 3) * 68 + rr + lr] = k4.w;
        }
        __syncthreads();

        float s[8][4] = {};
        #pragma unroll 4
        for (int d = 0; d < HDIM; d++) {
            float a[8], b[4];
            *(float4*)(a)     = *(const float4*)&Qt[d * 132 + ty * 8];
            *(float4*)(a + 4) = *(const float4*)&Qt[d * 132 + ty * 8 + 4];
            *(float4*)(b)     = *(const float4*)&KV[d * 68 + tx * 4];
            #pragma unroll
            for (int i = 0; i < 8; i++)
                #pragma unroll
                for (int j = 0; j < 4; j++)
                    s[i][j] += a[i] * b[j];
        }

        #pragma unroll
        for (int i = 0; i < 8; i++) {
            float tmax = fmaxf(fmaxf(s[i][0], s[i][1]), fmaxf(s[i][2], s[i][3]));
            #pragma unroll
            for (int off = 8; off; off >>= 1)
                tmax = fmaxf(tmax, __shfl_xor_sync(0xffffffffu, tmax, off, 16));
            tmax *= ATT_SCALE;
            const float mnew = fmaxf(mi[i], tmax);
            const float corr = __expf(mi[i] - mnew);
            float rsum = 0.f;
            #pragma unroll
            for (int j = 0; j < 4; j++) {
                float p = __expf(s[i][j] * ATT_SCALE - mnew);
                s[i][j] = p;
                rsum += p;
            }
            #pragma unroll
            for (int off = 8; off; off >>= 1)
                rsum += __shfl_xor_sync(0xffffffffu, rsum, off, 16);
            li[i] = li[i] * corr + rsum;
            mi[i] = mnew;
            O[i][0] *= corr; O[i][1] *= corr; O[i][2] *= corr; O[i][3] *= corr;
        }

        #pragma unroll
        for (int j = 0; j < 4; j++) {
            float4 p0 = make_float4(s[0][j], s[1][j], s[2][j], s[3][j]);
            float4 p1 = make_float4(s[4][j], s[5][j], s[6][j], s[7][j]);
            *(float4*)&Ps[(tx * 4 + j) * 132 + ty * 8]     = p0;
            *(float4*)&Ps[(tx * 4 + j) * 132 + ty * 8 + 4] = p1;
        }

        __syncthreads();
        #pragma unroll
        for (int rr = 0; rr < 64; rr += 16) {
            float4 v4 = *(const float4*)(Vb + (size_t)(k0 + rr + lr) * HDIM + lc);
            *(float4*)&KV[(rr + lr) * 68 + lc] = v4;
        }
        __syncthreads();

        #pragma unroll 4
        for (int k = 0; k < 64; k++) {
            float a[8], b[4];
            *(float4*)(a)     = *(const float4*)&Ps[k * 132 + ty * 8];
            *(float4*)(a + 4) = *(const float4*)&Ps[k * 132 + ty * 8 + 4];
            *(float4*)(b)     = *(const float4*)&KV[k * 68 + tx * 4];
            #pragma unroll
            for (int i = 0; i < 8; i++)
                #pragma unroll
                for (int j = 0; j < 4; j++)
                    O[i][j] += a[i] * b[j];
        }
    }

    const int b = bh >> 4, h = bh & 15;
    #pragma unroll
    for (int i = 0; i < 8; i++) {
        const float inv = 1.0f / li[i];
        const int row = q0 + ty * 8 + i;
        float4 o = make_float4(O[i][0] * inv, O[i][1] * inv,
                               O[i][2] * inv, O[i][3] * inv);
        *(float4*)&g_ao[((size_t)(b * SS + row)) * DD + h * HDIM + tx * 4] = o;
    }
}

// ---------------------------------------------------------------------------
extern "C" void kernel_launch(void* const* d_in, const int* in_sizes, int n_in,
                              void* d_out, int out_size)
{
    const float* x     = (const float*)d_in[0];
    const float* W_qkv = (const float*)d_in[1];
    const float* b_qkv = (const float*)d_in[2];
    const float* W_out = (const float*)d_in[3];
    const float* b_out = (const float*)d_in[4];
    float* out = (float*)d_out;

    const int gemm_smem = 2 * 4 * 16384;   // 131072
    cudaFuncSetAttribute(mma_gemm<true>,
                         cudaFuncAttributeMaxDynamicSharedMemorySize, gemm_smem);
    cudaFuncSetAttribute(mma_gemm<false>,
                         cudaFuncAttributeMaxDynamicSharedMemorySize, gemm_smem);

    __nv_bfloat16 *xh, *xl, *wqh, *wql, *woh, *wol, *aoh, *aol;
    float* ao;
    cudaGetSymbolAddress((void**)&xh,  g_xh);
    cudaGetSymbolAddress((void**)&xl,  g_xl);
    cudaGetSymbolAddress((void**)&wqh, g_wqkvh);
    cudaGetSymbolAddress((void**)&wql, g_wqkvl);
    cudaGetSymbolAddress((void**)&woh, g_wouth);
    cudaGetSymbolAddress((void**)&wol, g_woutl);
    cudaGetSymbolAddress((void**)&aoh, g_aoh);
    cudaGetSymbolAddress((void**)&aol, g_aol);
    cudaGetSymbolAddress((void**)&ao,  g_ao);

    // 0) prep: split x, transpose+split weights
    split_kernel<<<(M_TOT * DD / 4) / 256, 256>>>(
        (const float4*)x, (uint2*)xh, (uint2*)xl);
    transpose_split_kernel<<<dim3(N_QKV / 32, DD / 32), 256>>>(W_qkv, wqh, wql, N_QKV);
    transpose_split_kernel<<<dim3(DD / 32, DD / 32), 256>>>(W_out, woh, wol, DD);

    // 1) QKV projection (mma.sync split-bf16) + scatter
    mma_gemm<true><<<dim3(N_QKV / 128, M_TOT / 128), 256, gemm_smem>>>(
        xh, xl, wqh, wql, b_qkv, nullptr);

    // 2) flash attention (fp32 SIMT)
    const int attn_smem = (2 * 64 * 132 + 64 * 68) * (int)sizeof(float);
    cudaFuncSetAttribute(attn_kernel,
                         cudaFuncAttributeMaxDynamicSharedMemorySize, attn_smem);
    attn_kernel<<<dim3(SS / 128, BB * HH), 256, attn_smem>>>();

    // 3) split attention output, then output projection (mma.sync)
    split_kernel<<<(M_TOT * DD / 4) / 256, 256>>>(
        (const float4*)ao, (uint2*)aoh, (uint2*)aol);
    mma_gemm<false><<<dim3(DD / 128, M_TOT / 128), 256, gemm_smem>>>(
        aoh, aol, woh, wol, b_out, out);
}

// round 8
// speedup vs baseline: 3.1462x; 1.7760x over previous
#include <cuda_runtime.h>
#include <cuda_bf16.h>
#include <cstdint>

#define DD 1024
#define HH 16
#define HDIM 64
#define BB 2
#define SS 2048
#define M_TOT (BB*SS)      // 4096
#define N_QKV (3*DD)       // 3072
#define ATT_SCALE 0.125f   // 1/sqrt(64)

// ---------------------------------------------------------------------------
// scratch (allocation-free rule: device globals) — all bf16 hi/lo pairs
// ---------------------------------------------------------------------------
__device__ __align__(256) __nv_bfloat16 g_qh[BB*HH*SS*HDIM];  // [B,H,S,HD]
__device__ __align__(256) __nv_bfloat16 g_ql[BB*HH*SS*HDIM];
__device__ __align__(256) __nv_bfloat16 g_kh[BB*HH*SS*HDIM];
__device__ __align__(256) __nv_bfloat16 g_kl[BB*HH*SS*HDIM];
__device__ __align__(256) __nv_bfloat16 g_vh[BB*HH*SS*HDIM];
__device__ __align__(256) __nv_bfloat16 g_vl[BB*HH*SS*HDIM];

__device__ __align__(256) __nv_bfloat16 g_xh[(size_t)M_TOT*DD];
__device__ __align__(256) __nv_bfloat16 g_xl[(size_t)M_TOT*DD];
__device__ __align__(256) __nv_bfloat16 g_wqkvh[(size_t)N_QKV*DD];  // W^T [N][K]
__device__ __align__(256) __nv_bfloat16 g_wqkvl[(size_t)N_QKV*DD];
__device__ __align__(256) __nv_bfloat16 g_wouth[(size_t)DD*DD];
__device__ __align__(256) __nv_bfloat16 g_woutl[(size_t)DD*DD];
__device__ __align__(256) __nv_bfloat16 g_aoh[(size_t)M_TOT*DD];   // attn out [B*S][D]
__device__ __align__(256) __nv_bfloat16 g_aol[(size_t)M_TOT*DD];

// ---------------------------------------------------------------------------
// PTX helpers (base sm_80 ISA only — harness lowers through compute_103)
// ---------------------------------------------------------------------------
__device__ __forceinline__ uint32_t smem_to_u32(const void* p) {
    uint32_t a;
    asm("{ .reg .u64 t; cvta.to.shared.u64 t, %1; cvt.u32.u64 %0, t; }"
        : "=r"(a) : "l"(p));
    return a;
}
#define CP_ASYNC16(sm, gp) \
    asm volatile("cp.async.cg.shared.global [%0], [%1], 16;" :: "r"(sm), "l"(gp) : "memory")
#define CP_COMMIT() asm volatile("cp.async.commit_group;" ::: "memory")
#define CP_WAIT1()  asm volatile("cp.async.wait_group 1;" ::: "memory")
#define CP_WAIT0()  asm volatile("cp.async.wait_group 0;" ::: "memory")

#define SWZ128(o) ((o) ^ (((o) >> 3) & 0x70))

__device__ __forceinline__ void ldsm_x4(uint32_t& r0, uint32_t& r1,
                                        uint32_t& r2, uint32_t& r3, uint32_t a) {
    asm volatile("ldmatrix.sync.aligned.m8n8.x4.shared.b16 {%0,%1,%2,%3}, [%4];"
                 : "=r"(r0), "=r"(r1), "=r"(r2), "=r"(r3) : "r"(a));
}
__device__ __forceinline__ void ldsm_x4_t(uint32_t& r0, uint32_t& r1,
                                          uint32_t& r2, uint32_t& r3, uint32_t a) {
    asm volatile("ldmatrix.sync.aligned.m8n8.x4.trans.shared.b16 {%0,%1,%2,%3}, [%4];"
                 : "=r"(r0), "=r"(r1), "=r"(r2), "=r"(r3) : "r"(a));
}
__device__ __forceinline__ void mma16816(float* c, const uint32_t* a,
                                         const uint32_t* b) {
    asm volatile(
        "mma.sync.aligned.m16n8k16.row.col.f32.bf16.bf16.f32 "
        "{%0,%1,%2,%3}, {%4,%5,%6,%7}, {%8,%9}, {%0,%1,%2,%3};"
        : "+f"(c[0]), "+f"(c[1]), "+f"(c[2]), "+f"(c[3])
        : "r"(a[0]), "r"(a[1]), "r"(a[2]), "r"(a[3]), "r"(b[0]), "r"(b[1]));
}
// split fp32 pair -> packed bf16 hi pair (ret) and lo pair (out param)
__device__ __forceinline__ uint32_t pack_split(float v0, float v1, uint32_t& lo) {
    __nv_bfloat16 h0 = __float2bfloat16(v0), h1 = __float2bfloat16(v1);
    __nv_bfloat16 l0 = __float2bfloat16(v0 - __bfloat162float(h0));
    __nv_bfloat16 l1 = __float2bfloat16(v1 - __bfloat162float(h1));
    lo = (uint32_t)__bfloat16_as_ushort(l0) | ((uint32_t)__bfloat16_as_ushort(l1) << 16);
    return (uint32_t)__bfloat16_as_ushort(h0) | ((uint32_t)__bfloat16_as_ushort(h1) << 16);
}

// ---------------------------------------------------------------------------
// split / transpose prep kernels
// ---------------------------------------------------------------------------
__global__ __launch_bounds__(256) void split_kernel(
    const float4* __restrict__ in, uint2* __restrict__ hi, uint2* __restrict__ lo)
{
    int i = blockIdx.x * blockDim.x + threadIdx.x;
    float4 v = in[i];
    float vv[4] = {v.x, v.y, v.z, v.w};
    __nv_bfloat16 h[4], l[4];
    #pragma unroll
    for (int j = 0; j < 4; j++) {
        h[j] = __float2bfloat16(vv[j]);
        l[j] = __float2bfloat16(vv[j] - __bfloat162float(h[j]));
    }
    hi[i] = *(uint2*)h;
    lo[i] = *(uint2*)l;
}

// W[K][N] fp32 -> Wt_hi/lo [N][K=1024] bf16
__global__ __launch_bounds__(256) void transpose_split_kernel(
    const float* __restrict__ W, __nv_bfloat16* __restrict__ Th,
    __nv_bfloat16* __restrict__ Tl, int N)
{
    __shared__ float t[32][33];
    const int k0 = blockIdx.y * 32, n0 = blockIdx.x * 32;
    const int tx = threadIdx.x & 31, ty = threadIdx.x >> 5;
    #pragma unroll
    for (int j = 0; j < 4; j++)
        t[ty + j * 8][tx] = W[(size_t)(k0 + ty + j * 8) * N + n0 + tx];
    __syncthreads();
    #pragma unroll
    for (int j = 0; j < 4; j++) {
        const int n = n0 + ty + j * 8;
        float v = t[tx][ty + j * 8];
        __nv_bfloat16 h = __float2bfloat16(v);
        __nv_bfloat16 l = __float2bfloat16(v - __bfloat162float(h));
        Th[(size_t)n * DD + k0 + tx] = h;
        Tl[(size_t)n * DD + k0 + tx] = l;
    }
}

// ---------------------------------------------------------------------------
// mma.sync split-bf16 GEMM (proven R7 core).
// QKV=true: epilogue splits result to bf16 hi/lo and scatters into g_{q,k,v}{h,l}.
// QKV=false: fp32 epilogue into C.
// ---------------------------------------------------------------------------
template<bool QKV>
__global__ __launch_bounds__(256)
void mma_gemm(const __nv_bfloat16* __restrict__ Ah,
              const __nv_bfloat16* __restrict__ Al,
              const __nv_bfloat16* __restrict__ Bh,
              const __nv_bfloat16* __restrict__ Bl,
              const float* __restrict__ bias,
              float* __restrict__ C)
{
    extern __shared__ char smem[];
    const uint32_t sm0 = smem_to_u32(smem);

    const int tid = threadIdx.x;
    const int wid = tid >> 5, lane = tid & 31;
    const int m0 = blockIdx.y * 128, n0 = blockIdx.x * 128;
    const int wm = wid & 1;
    const int wn = wid >> 1;

    const char* srcs[4] = {
        (const char*)(Ah + (size_t)m0 * DD),
        (const char*)(Al + (size_t)m0 * DD),
        (const char*)(Bh + (size_t)n0 * DD),
        (const char*)(Bl + (size_t)n0 * DD)
    };

    auto load_stage = [&](int stage, int chunk) {
        const uint32_t sbase = sm0 + stage * 65536;
        const size_t coff = (size_t)chunk * 128;
        #pragma unroll
        for (int t = 0; t < 4; t++) {
            const uint32_t tb = sbase + t * 16384;
            #pragma unroll
            for (int j = 0; j < 4; j++) {
                const int g = tid + j * 256;
                const int r = g >> 3;
                const uint32_t cb = (uint32_t)((g & 7) * 16);
                const uint32_t so = tb + SWZ128((uint32_t)(r * 128) + cb);
                const char* gp = srcs[t] + (size_t)r * (DD * 2) + coff + cb;
                CP_ASYNC16(so, gp);
            }
        }
        CP_COMMIT();
    };

    load_stage(0, 0);
    load_stage(1, 1);

    float acc[4][4][4] = {};

    const int sub   = lane >> 3;
    const int a_rin = (lane & 7) + (sub & 1) * 8;
    const int a_kh  = sub >> 1;
    const int b_nt  = sub >> 1;
    const int b_kh  = sub & 1;
    const int b_row = lane & 7;

    const int K_CHUNKS = DD / 64;  // 16
    for (int i = 0; i < K_CHUNKS; i++) {
        const int stage = i & 1;
        if (i + 1 < K_CHUNKS) { CP_WAIT1(); } else { CP_WAIT0(); }
        __syncthreads();

        const uint32_t sb  = sm0 + stage * 65536;
        const uint32_t Ahb = sb, Alb = sb + 16384, Bhb = sb + 32768, Blb = sb + 49152;

        #pragma unroll
        for (int ks = 0; ks < 4; ks++) {
            uint32_t ahf[4][4], alf[4][4], bhf[4][2], blf[4][2];
            const uint32_t gka = (uint32_t)((ks * 2 + a_kh) * 16);
            #pragma unroll
            for (int mt = 0; mt < 4; mt++) {
                const uint32_t off =
                    SWZ128((uint32_t)((wm * 64 + mt * 16 + a_rin) * 128) + gka);
                ldsm_x4(ahf[mt][0], ahf[mt][1], ahf[mt][2], ahf[mt][3], Ahb + off);
                ldsm_x4(alf[mt][0], alf[mt][1], alf[mt][2], alf[mt][3], Alb + off);
            }
            const uint32_t gkb = (uint32_t)((ks * 2 + b_kh) * 16);
            #pragma unroll
            for (int pr = 0; pr < 2; pr++) {
                const uint32_t off =
                    SWZ128((uint32_t)((wn * 32 + pr * 16 + b_nt * 8 + b_row) * 128) + gkb);
                uint32_t r0, r1, r2, r3;
                ldsm_x4(r0, r1, r2, r3, Bhb + off);
                bhf[pr * 2][0] = r0; bhf[pr * 2][1] = r1;
                bhf[pr * 2 + 1][0] = r2; bhf[pr * 2 + 1][1] = r3;
                ldsm_x4(r0, r1, r2, r3, Blb + off);
                blf[pr * 2][0] = r0; blf[pr * 2][1] = r1;
                blf[pr * 2 + 1][0] = r2; blf[pr * 2 + 1][1] = r3;
            }
            #pragma unroll
            for (int mt = 0; mt < 4; mt++)
                #pragma unroll
                for (int nt = 0; nt < 4; nt++) {
                    mma16816(acc[mt][nt], ahf[mt], bhf[nt]);
                    mma16816(acc[mt][nt], ahf[mt], blf[nt]);
                    mma16816(acc[mt][nt], alf[mt], bhf[nt]);
                }
        }
        __syncthreads();
        if (i + 2 < K_CHUNKS) load_stage(stage, i + 2);
    }

    const int cg = lane >> 2, ctg = lane & 3;
    const int nb = n0 + wn * 32;

    if (QKV) {
        const int tsel = nb >> 10;
        const int h = (nb & 1023) >> 6;
        const int db = nb & 63;
        __nv_bfloat16* dh = (tsel == 0) ? g_qh : (tsel == 1) ? g_kh : g_vh;
        __nv_bfloat16* dl = (tsel == 0) ? g_ql : (tsel == 1) ? g_kl : g_vl;
        #pragma unroll
        for (int mt = 0; mt < 4; mt++) {
            const int ma = m0 + wm * 64 + mt * 16 + cg;
            const int mb = ma + 8;
            const int ba = ma >> 11, sa = ma & 2047;
            const int bb = mb >> 11, sbb = mb & 2047;
            const size_t ra = (((size_t)(ba * HH + h)) * SS + sa) * HDIM + db;
            const size_t rb = (((size_t)(bb * HH + h)) * SS + sbb) * HDIM + db;
            #pragma unroll
            for (int nt = 0; nt < 4; nt++) {
                const int cc = nt * 8 + ctg * 2;
                float2 bv = *(const float2*)(bias + nb + cc);
                uint32_t lo, hi;
                hi = pack_split(acc[mt][nt][0] + bv.x, acc[mt][nt][1] + bv.y, lo);
                *(uint32_t*)(dh + ra + cc) = hi;
                *(uint32_t*)(dl + ra + cc) = lo;
                hi = pack_split(acc[mt][nt][2] + bv.x, acc[mt][nt][3] + bv.y, lo);
                *(uint32_t*)(dh + rb + cc) = hi;
                *(uint32_t*)(dl + rb + cc) = lo;
            }
        }
    } else {
        #pragma unroll
        for (int mt = 0; mt < 4; mt++) {
            const int ma = m0 + wm * 64 + mt * 16 + cg;
            float* pa = C + (size_t)ma * DD + nb;
            float* pb = C + (size_t)(ma + 8) * DD + nb;
            #pragma unroll
            for (int nt = 0; nt < 4; nt++) {
                const int cc = nt * 8 + ctg * 2;
                float2 bv = *(const float2*)(bias + nb + cc);
                float2 v0 = make_float2(acc[mt][nt][0] + bv.x, acc[mt][nt][1] + bv.y);
                float2 v1 = make_float2(acc[mt][nt][2] + bv.x, acc[mt][nt][3] + bv.y);
                *(float2*)(pa + cc) = v0;
                *(float2*)(pb + cc) = v1;
            }
        }
    }
}

// ---------------------------------------------------------------------------
// Flash attention on mma.sync. 128-query CTA tile, 8 warps x 16 rows,
// key tiles of 64, split-bf16 3-product MMAs for both S=QK^T and O+=PV.
// smem: Qh 0, Ql 16K, Ph 32K, Pl 48K, stages at 64K (Kh,Kl,Vh,Vl 8K each) x2.
// ---------------------------------------------------------------------------
__global__ __launch_bounds__(256)
void attn_mma_kernel()
{
    extern __shared__ char smem[];
    const uint32_t sm0 = smem_to_u32(smem);

    const int tid = threadIdx.x;
    const int w = tid >> 5, lane = tid & 31;
    const int bh = blockIdx.y;
    const int q0 = blockIdx.x * 128;

    const size_t bho = (size_t)bh * SS * HDIM;
    const char* qsrc[2] = {
        (const char*)(g_qh + bho + (size_t)q0 * HDIM),
        (const char*)(g_ql + bho + (size_t)q0 * HDIM)
    };
    const char* kvsrc[4] = {
        (const char*)(g_kh + bho), (const char*)(g_kl + bho),
        (const char*)(g_vh + bho), (const char*)(g_vl + bho)
    };

    // Q tiles: 128 rows x 128B, hi/lo
    #pragma unroll
    for (int t = 0; t < 2; t++) {
        #pragma unroll
        for (int j = 0; j < 4; j++) {
            const int g = tid + j * 256;           // 1024 granules
            const int r = g >> 3;
            const uint32_t cb = (uint32_t)((g & 7) * 16);
            CP_ASYNC16(sm0 + t * 16384 + SWZ128((uint32_t)(r * 128) + cb),
                       qsrc[t] + (size_t)r * 128 + cb);
        }
    }
    CP_COMMIT();

    auto load_kv = [&](int stage, int kt) {
        const uint32_t sb = sm0 + 65536 + stage * 32768;
        const size_t roff = (size_t)(kt * 64) * 128;   // bytes
        #pragma unroll
        for (int t = 0; t < 4; t++) {
            #pragma unroll
            for (int j = 0; j < 2; j++) {
                const int g = tid + j * 256;       // 512 granules (64 rows x 8)
                const int r = g >> 3;
                const uint32_t cb = (uint32_t)((g & 7) * 16);
                CP_ASYNC16(sb + t * 8192 + SWZ128((uint32_t)(r * 128) + cb),
                           kvsrc[t] + roff + (size_t)r * 128 + cb);
            }
        }
        CP_COMMIT();
    };

    load_kv(0, 0);
    load_kv(1, 1);

    const int sub   = lane >> 3;
    const int a_rin = (lane & 7) + (sub & 1) * 8;
    const int a_kh  = sub >> 1;
    const int b_nt  = sub >> 1;
    const int b_kh  = sub & 1;
    const int b_row = lane & 7;
    const int v_row = lane & 15;
    const int v_col = (lane >> 4) * 8;
    const int cg = lane >> 2, ctg = lane & 3;

    float acc_o[8][4] = {};
    float mi0 = -1e30f, mi1 = -1e30f, li0 = 0.f, li1 = 0.f;

    const int KT = SS / 64;  // 32
    for (int kt = 0; kt < KT; kt++) {
        const int stage = kt & 1;
        if (kt + 1 < KT) { CP_WAIT1(); } else { CP_WAIT0(); }
        __syncthreads();

        const uint32_t Khb = sm0 + 65536 + stage * 32768;
        const uint32_t Klb = Khb + 8192, Vhb = Khb + 16384, Vlb = Khb + 24576;

        // ---- S = Q K^T (split 3-product) ----
        float acc_s[8][4] = {};
        #pragma unroll
        for (int ks = 0; ks < 4; ks++) {
            uint32_t ah[4], al[4];
            const uint32_t offa =
                SWZ128((uint32_t)((w * 16 + a_rin) * 128 + (ks * 2 + a_kh) * 16));
            ldsm_x4(ah[0], ah[1], ah[2], ah[3], sm0 + offa);
            ldsm_x4(al[0], al[1], al[2], al[3], sm0 + 16384 + offa);
            #pragma unroll
            for (int pr = 0; pr < 4; pr++) {
                const uint32_t offb =
                    SWZ128((uint32_t)((pr * 16 + b_nt * 8 + b_row) * 128 + (ks * 2 + b_kh) * 16));
                uint32_t h0, h1, h2, h3, l0, l1, l2, l3;
                ldsm_x4(h0, h1, h2, h3, Khb + offb);
                ldsm_x4(l0, l1, l2, l3, Klb + offb);
                uint32_t bh0[2] = {h0, h1}, bh1[2] = {h2, h3};
                uint32_t bl0[2] = {l0, l1}, bl1[2] = {l2, l3};
                mma16816(acc_s[2 * pr],     ah, bh0);
                mma16816(acc_s[2 * pr],     al, bh0);
                mma16816(acc_s[2 * pr],     ah, bl0);
                mma16816(acc_s[2 * pr + 1], ah, bh1);
                mma16816(acc_s[2 * pr + 1], al, bh1);
                mma16816(acc_s[2 * pr + 1], ah, bl1);
            }
        }

        // ---- online softmax (rows cg, cg+8; quad shfl reductions) ----
        float t0 = -1e30f, t1 = -1e30f;
        #pragma unroll
        for (int nt = 0; nt < 8; nt++) {
            t0 = fmaxf(t0, fmaxf(acc_s[nt][0], acc_s[nt][1]));
            t1 = fmaxf(t1, fmaxf(acc_s[nt][2], acc_s[nt][3]));
        }
        t0 = fmaxf(t0, __shfl_xor_sync(0xffffffffu, t0, 1));
        t0 = fmaxf(t0, __shfl_xor_sync(0xffffffffu, t0, 2));
        t1 = fmaxf(t1, __shfl_xor_sync(0xffffffffu, t1, 1));
        t1 = fmaxf(t1, __shfl_xor_sync(0xffffffffu, t1, 2));
        const float mn0 = fmaxf(mi0, t0 * ATT_SCALE);
        const float mn1 = fmaxf(mi1, t1 * ATT_SCALE);
        const float c0 = __expf(mi0 - mn0), c1 = __expf(mi1 - mn1);
        float rs0 = 0.f, rs1 = 0.f;
        #pragma unroll
        for (int nt = 0; nt < 8; nt++) {
            float p;
            p = __expf(acc_s[nt][0] * ATT_SCALE - mn0); acc_s[nt][0] = p; rs0 += p;
            p = __expf(acc_s[nt][1] * ATT_SCALE - mn0); acc_s[nt][1] = p; rs0 += p;
            p = __expf(acc_s[nt][2] * ATT_SCALE - mn1); acc_s[nt][2] = p; rs1 += p;
            p = __expf(acc_s[nt][3] * ATT_SCALE - mn1); acc_s[nt][3] = p; rs1 += p;
        }
        rs0 += __shfl_xor_sync(0xffffffffu, rs0, 1);
        rs0 += __shfl_xor_sync(0xffffffffu, rs0, 2);
        rs1 += __shfl_xor_sync(0xffffffffu, rs1, 1);
        rs1 += __shfl_xor_sync(0xffffffffu, rs1, 2);
        li0 = li0 * c0 + rs0;  li1 = li1 * c1 + rs1;
        mi0 = mn0;  mi1 = mn1;
        #pragma unroll
        for (int nt = 0; nt < 8; nt++) {
            acc_o[nt][0] *= c0; acc_o[nt][1] *= c0;
            acc_o[nt][2] *= c1; acc_o[nt][3] *= c1;
        }

        // ---- write P hi/lo to smem ----
        #pragma unroll
        for (int nt = 0; nt < 8; nt++) {
            uint32_t lo, hi;
            const uint32_t off0 =
                SWZ128((uint32_t)((w * 16 + cg) * 128 + (nt * 8 + ctg * 2) * 2));
            hi = pack_split(acc_s[nt][0], acc_s[nt][1], lo);
            *(uint32_t*)(smem + 32768 + off0) = hi;
            *(uint32_t*)(smem + 49152 + off0) = lo;
            const uint32_t off1 =
                SWZ128((uint32_t)((w * 16 + cg + 8) * 128 + (nt * 8 + ctg * 2) * 2));
            hi = pack_split(acc_s[nt][2], acc_s[nt][3], lo);
            *(uint32_t*)(smem + 32768 + off1) = hi;
            *(uint32_t*)(smem + 49152 + off1) = lo;
        }
        __syncthreads();

        // ---- O += P V (V fragments via ldmatrix.trans on natural [key][dim]) ----
        #pragma unroll
        for (int ks = 0; ks < 4; ks++) {
            uint32_t ah[4], al[4];
            const uint32_t offa =
                SWZ128((uint32_t)((w * 16 + a_rin) * 128 + (ks * 2 + a_kh) * 16));
            ldsm_x4(ah[0], ah[1], ah[2], ah[3], sm0 + 32768 + offa);
            ldsm_x4(al[0], al[1], al[2], al[3], sm0 + 49152 + offa);
            #pragma unroll
            for (int pr = 0; pr < 4; pr++) {
                const uint32_t offv =
                    SWZ128((uint32_t)((ks * 16 + v_row) * 128 + (pr * 16 + v_col) * 2));
                uint32_t h0, h1, h2, h3, l0, l1, l2, l3;
                ldsm_x4_t(h0, h1, h2, h3, Vhb + offv);
                ldsm_x4_t(l0, l1, l2, l3, Vlb + offv);
                uint32_t bh0[2] = {h0, h1}, bh1[2] = {h2, h3};
                uint32_t bl0[2] = {l0, l1}, bl1[2] = {l2, l3};
                mma16816(acc_o[2 * pr],     ah, bh0);
                mma16816(acc_o[2 * pr],     al, bh0);
                mma16816(acc_o[2 * pr],     ah, bl0);
                mma16816(acc_o[2 * pr + 1], ah, bh1);
                mma16816(acc_o[2 * pr + 1], al, bh1);
                mma16816(acc_o[2 * pr + 1], ah, bl1);
            }
        }

        if (kt + 2 < KT) {
            __syncthreads();            // all warps done reading V before refill
            load_kv(stage, kt + 2);
        }
    }

    // ---- epilogue: normalize, split hi/lo, write to g_ao{h,l} ----
    const int b = bh >> 4, hd = bh & 15;
    const float inv0 = 1.0f / li0, inv1 = 1.0f / li1;
    const int r0 = q0 + w * 16 + cg, r1 = r0 + 8;
    const size_t base0 = ((size_t)(b * SS + r0)) * DD + hd * HDIM;
    const size_t base1 = ((size_t)(b * SS + r1)) * DD + hd * HDIM;
    #pragma unroll
    for (int nt = 0; nt < 8; nt++) {
        const int cc = nt * 8 + ctg * 2;
        uint32_t lo, hi;
        hi = pack_split(acc_o[nt][0] * inv0, acc_o[nt][1] * inv0, lo);
        *(uint32_t*)(g_aoh + base0 + cc) = hi;
        *(uint32_t*)(g_aol + base0 + cc) = lo;
        hi = pack_split(acc_o[nt][2] * inv1, acc_o[nt][3] * inv1, lo);
        *(uint32_t*)(g_aoh + base1 + cc) = hi;
        *(uint32_t*)(g_aol + base1 + cc) = lo;
    }
}

// ---------------------------------------------------------------------------
extern "C" void kernel_launch(void* const* d_in, const int* in_sizes, int n_in,
                              void* d_out, int out_size)
{
    const float* x     = (const float*)d_in[0];
    const float* W_qkv = (const float*)d_in[1];
    const float* b_qkv = (const float*)d_in[2];
    const float* W_out = (const float*)d_in[3];
    const float* b_out = (const float*)d_in[4];
    float* out = (float*)d_out;

    const int gemm_smem = 2 * 4 * 16384;   // 131072
    const int attn_smem = 4 * 16384 + 2 * 32768;  // 131072
    cudaFuncSetAttribute(mma_gemm<true>,
                         cudaFuncAttributeMaxDynamicSharedMemorySize, gemm_smem);
    cudaFuncSetAttribute(mma_gemm<false>,
                         cudaFuncAttributeMaxDynamicSharedMemorySize, gemm_smem);
    cudaFuncSetAttribute(attn_mma_kernel,
                         cudaFuncAttributeMaxDynamicSharedMemorySize, attn_smem);

    __nv_bfloat16 *xh, *xl, *wqh, *wql, *woh, *wol, *aoh, *aol;
    cudaGetSymbolAddress((void**)&xh,  g_xh);
    cudaGetSymbolAddress((void**)&xl,  g_xl);
    cudaGetSymbolAddress((void**)&wqh, g_wqkvh);
    cudaGetSymbolAddress((void**)&wql, g_wqkvl);
    cudaGetSymbolAddress((void**)&woh, g_wouth);
    cudaGetSymbolAddress((void**)&wol, g_woutl);
    cudaGetSymbolAddress((void**)&aoh, g_aoh);
    cudaGetSymbolAddress((void**)&aol, g_aol);

    // 0) prep: split x, transpose+split weights
    split_kernel<<<(M_TOT * DD / 4) / 256, 256>>>(
        (const float4*)x, (uint2*)xh, (uint2*)xl);
    transpose_split_kernel<<<dim3(N_QKV / 32, DD / 32), 256>>>(W_qkv, wqh, wql, N_QKV);
    transpose_split_kernel<<<dim3(DD / 32, DD / 32), 256>>>(W_out, woh, wol, DD);

    // 1) QKV projection -> bf16 hi/lo Q,K,V in [B,H,S,HD]
    mma_gemm<true><<<dim3(N_QKV / 128, M_TOT / 128), 256, gemm_smem>>>(
        xh, xl, wqh, wql, b_qkv, nullptr);

    // 2) flash attention (mma.sync) -> bf16 hi/lo ao
    attn_mma_kernel<<<dim3(SS / 128, BB * HH), 256, attn_smem>>>();

    // 3) output projection (fp32 out)
    mma_gemm<false><<<dim3(DD / 128, M_TOT / 128), 256, gemm_smem>>>(
        aoh, aol, woh, wol, b_out, out);
}

// round 10
// speedup vs baseline: 4.8588x; 1.5443x over previous
#include <cuda_runtime.h>
#include <cuda_bf16.h>
#include <cuda_fp16.h>
#include <cstdint>

#define DD 1024
#define HH 16
#define HDIM 64
#define BB 2
#define SS 2048
#define M_TOT (BB*SS)      // 4096
#define N_QKV (3*DD)       // 3072
#define ATT_SCALE 0.125f   // 1/sqrt(64)

// ---------------------------------------------------------------------------
// scratch (allocation-free rule: device globals)
// ---------------------------------------------------------------------------
__device__ __align__(256) __half g_qf[BB*HH*SS*HDIM];   // [B,H,S,HD] fp16
__device__ __align__(256) __half g_kf[BB*HH*SS*HDIM];
__device__ __align__(256) __half g_vf[BB*HH*SS*HDIM];

__device__ __align__(256) __nv_bfloat16 g_xh[(size_t)M_TOT*DD];
__device__ __align__(256) __nv_bfloat16 g_xl[(size_t)M_TOT*DD];
__device__ __align__(256) __nv_bfloat16 g_wqkvh[(size_t)N_QKV*DD];  // W^T [N][K]
__device__ __align__(256) __nv_bfloat16 g_wqkvl[(size_t)N_QKV*DD];
__device__ __align__(256) __nv_bfloat16 g_wouth[(size_t)DD*DD];
__device__ __align__(256) __nv_bfloat16 g_woutl[(size_t)DD*DD];
__device__ __align__(256) __nv_bfloat16 g_aoh[(size_t)M_TOT*DD];   // attn out [B*S][D]
__device__ __align__(256) __nv_bfloat16 g_aol[(size_t)M_TOT*DD];

// ---------------------------------------------------------------------------
// PTX helpers (base sm_80 ISA — harness lowers through compute_103)
// ---------------------------------------------------------------------------
__device__ __forceinline__ uint32_t smem_to_u32(const void* p) {
    uint32_t a;
    asm("{ .reg .u64 t; cvta.to.shared.u64 t, %1; cvt.u32.u64 %0, t; }"
        : "=r"(a) : "l"(p));
    return a;
}
#define CP_ASYNC16(sm, gp) \
    asm volatile("cp.async.cg.shared.global [%0], [%1], 16;" :: "r"(sm), "l"(gp) : "memory")
#define CP_COMMIT() asm volatile("cp.async.commit_group;" ::: "memory")
#define CP_WAIT2()  asm volatile("cp.async.wait_group 2;" ::: "memory")
#define CP_WAIT1()  asm volatile("cp.async.wait_group 1;" ::: "memory")
#define CP_WAIT0()  asm volatile("cp.async.wait_group 0;" ::: "memory")

#define SWZ128(o) ((o) ^ (((o) >> 3) & 0x70))

__device__ __forceinline__ void ldsm_x4(uint32_t& r0, uint32_t& r1,
                                        uint32_t& r2, uint32_t& r3, uint32_t a) {
    asm volatile("ldmatrix.sync.aligned.m8n8.x4.shared.b16 {%0,%1,%2,%3}, [%4];"
                 : "=r"(r0), "=r"(r1), "=r"(r2), "=r"(r3) : "r"(a));
}
__device__ __forceinline__ void ldsm_x4_t(uint32_t& r0, uint32_t& r1,
                                          uint32_t& r2, uint32_t& r3, uint32_t a) {
    asm volatile("ldmatrix.sync.aligned.m8n8.x4.trans.shared.b16 {%0,%1,%2,%3}, [%4];"
                 : "=r"(r0), "=r"(r1), "=r"(r2), "=r"(r3) : "r"(a));
}
__device__ __forceinline__ void mma16816(float* c, const uint32_t* a,
                                         const uint32_t* b) {
    asm volatile(
        "mma.sync.aligned.m16n8k16.row.col.f32.bf16.bf16.f32 "
        "{%0,%1,%2,%3}, {%4,%5,%6,%7}, {%8,%9}, {%0,%1,%2,%3};"
        : "+f"(c[0]), "+f"(c[1]), "+f"(c[2]), "+f"(c[3])
        : "r"(a[0]), "r"(a[1]), "r"(a[2]), "r"(a[3]), "r"(b[0]), "r"(b[1]));
}
__device__ __forceinline__ void mma16816h(float* c, const uint32_t* a,
                                          const uint32_t* b) {
    asm volatile(
        "mma.sync.aligned.m16n8k16.row.col.f32.f16.f16.f32 "
        "{%0,%1,%2,%3}, {%4,%5,%6,%7}, {%8,%9}, {%0,%1,%2,%3};"
        : "+f"(c[0]), "+f"(c[1]), "+f"(c[2]), "+f"(c[3])
        : "r"(a[0]), "r"(a[1]), "r"(a[2]), "r"(a[3]), "r"(b[0]), "r"(b[1]));
}
// pack two fp32 -> half2 (lo = v0, hi = v1)
__device__ __forceinline__ uint32_t pack_h2(float v0, float v1) {
    uint32_t r;
    asm("cvt.rn.f16x2.f32 %0, %1, %2;" : "=r"(r) : "f"(v1), "f"(v0));
    return r;
}
// split fp32 pair -> packed bf16 hi pair (ret) and lo pair (out param)
__device__ __forceinline__ uint32_t pack_split(float v0, float v1, uint32_t& lo) {
    __nv_bfloat16 h0 = __float2bfloat16(v0), h1 = __float2bfloat16(v1);
    __nv_bfloat16 l0 = __float2bfloat16(v0 - __bfloat162float(h0));
    __nv_bfloat16 l1 = __float2bfloat16(v1 - __bfloat162float(h1));
    lo = (uint32_t)__bfloat16_as_ushort(l0) | ((uint32_t)__bfloat16_as_ushort(l1) << 16);
    return (uint32_t)__bfloat16_as_ushort(h0) | ((uint32_t)__bfloat16_as_ushort(h1) << 16);
}

// ---------------------------------------------------------------------------
// split / transpose prep kernels
// ---------------------------------------------------------------------------
__global__ __launch_bounds__(256) void split_kernel(
    const float4* __restrict__ in, uint2* __restrict__ hi, uint2* __restrict__ lo)
{
    int i = blockIdx.x * blockDim.x + threadIdx.x;
    float4 v = in[i];
    float vv[4] = {v.x, v.y, v.z, v.w};
    __nv_bfloat16 h[4], l[4];
    #pragma unroll
    for (int j = 0; j < 4; j++) {
        h[j] = __float2bfloat16(vv[j]);
        l[j] = __float2bfloat16(vv[j] - __bfloat162float(h[j]));
    }
    hi[i] = *(uint2*)h;
    lo[i] = *(uint2*)l;
}

// W[K][N] fp32 -> Wt_hi/lo [N][K=1024] bf16
__global__ __launch_bounds__(256) void transpose_split_kernel(
    const float* __restrict__ W, __nv_bfloat16* __restrict__ Th,
    __nv_bfloat16* __restrict__ Tl, int N)
{
    __shared__ float t[32][33];
    const int k0 = blockIdx.y * 32, n0 = blockIdx.x * 32;
    const int tx = threadIdx.x & 31, ty = threadIdx.x >> 5;
    #pragma unroll
    for (int j = 0; j < 4; j++)
        t[ty + j * 8][tx] = W[(size_t)(k0 + ty + j * 8) * N + n0 + tx];
    __syncthreads();
    #pragma unroll
    for (int j = 0; j < 4; j++) {
        const int n = n0 + ty + j * 8;
        float v = t[tx][ty + j * 8];
        __nv_bfloat16 h = __float2bfloat16(v);
        __nv_bfloat16 l = __float2bfloat16(v - __bfloat162float(h));
        Th[(size_t)n * DD + k0 + tx] = h;
        Tl[(size_t)n * DD + k0 + tx] = l;
    }
}

// ---------------------------------------------------------------------------
// mma.sync split-bf16 GEMM, 512 threads (16 warps, 32x32 tiles), 3-stage
// cp.async pipeline. QKV=true: epilogue packs result to fp16 and scatters
// into g_{q,k,v}f. QKV=false: fp32 epilogue into C.
// ---------------------------------------------------------------------------
template<bool QKV>
__global__ __launch_bounds__(512)
void mma_gemm(const __nv_bfloat16* __restrict__ Ah,
              const __nv_bfloat16* __restrict__ Al,
              const __nv_bfloat16* __restrict__ Bh,
              const __nv_bfloat16* __restrict__ Bl,
              const float* __restrict__ bias,
              float* __restrict__ C)
{
    extern __shared__ char smem[];
    const uint32_t sm0 = smem_to_u32(smem);   // stage s: +s*65536, tile t: +t*16384

    const int tid = threadIdx.x;
    const int wid = tid >> 5, lane = tid & 31;
    const int m0 = blockIdx.y * 128, n0 = blockIdx.x * 128;
    const int wm = wid & 3;     // 4 row groups of 32
    const int wn = wid >> 2;    // 4 col groups of 32

    const char* srcs[4] = {
        (const char*)(Ah + (size_t)m0 * DD),
        (const char*)(Al + (size_t)m0 * DD),
        (const char*)(Bh + (size_t)n0 * DD),
        (const char*)(Bl + (size_t)n0 * DD)
    };

    auto load_stage = [&](int stage, int chunk) {
        const uint32_t sbase = sm0 + stage * 65536;
        const size_t coff = (size_t)chunk * 128;
        #pragma unroll
        for (int t = 0; t < 4; t++) {
            const uint32_t tb = sbase + t * 16384;
            #pragma unroll
            for (int j = 0; j < 2; j++) {
                const int g = tid + j * 512;          // 1024 granules of 16B
                const int r = g >> 3;
                const uint32_t cb = (uint32_t)((g & 7) * 16);
                CP_ASYNC16(tb + SWZ128((uint32_t)(r * 128) + cb),
                           srcs[t] + (size_t)r * (DD * 2) + coff + cb);
            }
        }
        CP_COMMIT();
    };

    load_stage(0, 0);
    load_stage(1, 1);
    load_stage(2, 2);

    float acc[2][4][4] = {};

    const int sub   = lane >> 3;
    const int a_rin = (lane & 7) + (sub & 1) * 8;
    const int a_kh  = sub >> 1;
    const int b_nt  = sub >> 1;
    const int b_kh  = sub & 1;
    const int b_row = lane & 7;

    const int K_CHUNKS = DD / 64;  // 16
    for (int i = 0; i < K_CHUNKS; i++) {
        const int stage = i % 3;
        if (i <= K_CHUNKS - 3)      { CP_WAIT2(); }
        else if (i == K_CHUNKS - 2) { CP_WAIT1(); }
        else                        { CP_WAIT0(); }
        __syncthreads();

        const uint32_t sb  = sm0 + stage * 65536;
        const uint32_t Ahb = sb, Alb = sb + 16384, Bhb = sb + 32768, Blb = sb + 49152;

        #pragma unroll
        for (int ks = 0; ks < 4; ks++) {
            uint32_t ahf[2][4], alf[2][4], bhf[4][2], blf[4][2];
            const uint32_t gka = (uint32_t)((ks * 2 + a_kh) * 16);
            #pragma unroll
            for (int mt = 0; mt < 2; mt++) {
                const uint32_t off =
                    SWZ128((uint32_t)((wm * 32 + mt * 16 + a_rin) * 128) + gka);
                ldsm_x4(ahf[mt][0], ahf[mt][1], ahf[mt][2], ahf[mt][3], Ahb + off);
                ldsm_x4(alf[mt][0], alf[mt][1], alf[mt][2], alf[mt][3], Alb + off);
            }
            const uint32_t gkb = (uint32_t)((ks * 2 + b_kh) * 16);
            #pragma unroll
            for (int pr = 0; pr < 2; pr++) {
                const uint32_t off =
                    SWZ128((uint32_t)((wn * 32 + pr * 16 + b_nt * 8 + b_row) * 128) + gkb);
                uint32_t r0, r1, r2, r3;
                ldsm_x4(r0, r1, r2, r3, Bhb + off);
                bhf[pr * 2][0] = r0; bhf[pr * 2][1] = r1;
                bhf[pr * 2 + 1][0] = r2; bhf[pr * 2 + 1][1] = r3;
                ldsm_x4(r0, r1, r2, r3, Blb + off);
                blf[pr * 2][0] = r0; blf[pr * 2][1] = r1;
                blf[pr * 2 + 1][0] = r2; blf[pr * 2 + 1][1] = r3;
            }
            #pragma unroll
            for (int mt = 0; mt < 2; mt++)
                #pragma unroll
                for (int nt = 0; nt < 4; nt++) {
                    mma16816(acc[mt][nt], ahf[mt], bhf[nt]);
                    mma16816(acc[mt][nt], ahf[mt], blf[nt]);
                    mma16816(acc[mt][nt], alf[mt], bhf[nt]);
                }
        }
        __syncthreads();
        if (i + 3 < K_CHUNKS) load_stage(stage, i + 3);
    }

    const int cg = lane >> 2, ctg = lane & 3;
    const int nb = n0 + wn * 32;

    if (QKV) {
        const int tsel = nb >> 10;
        const int h = (nb & 1023) >> 6;
        const int db = nb & 63;
        __half* dst = (tsel == 0) ? g_qf : (tsel == 1) ? g_kf : g_vf;
        #pragma unroll
        for (int mt = 0; mt < 2; mt++) {
            const int ma = m0 + wm * 32 + mt * 16 + cg;
            const int mb = ma + 8;
            const int ba = ma >> 11, sa = ma & 2047;
            const int bb = mb >> 11, sbb = mb & 2047;
            const size_t ra = (((size_t)(ba * HH + h)) * SS + sa) * HDIM + db;
            const size_t rb = (((size_t)(bb * HH + h)) * SS + sbb) * HDIM + db;
            #pragma unroll
            for (int nt = 0; nt < 4; nt++) {
                const int cc = nt * 8 + ctg * 2;
                float2 bv = *(const float2*)(bias + nb + cc);
                *(uint32_t*)(dst + ra + cc) =
                    pack_h2(acc[mt][nt][0] + bv.x, acc[mt][nt][1] + bv.y);
                *(uint32_t*)(dst + rb + cc) =
                    pack_h2(acc[mt][nt][2] + bv.x, acc[mt][nt][3] + bv.y);
            }
        }
    } else {
        #pragma unroll
        for (int mt = 0; mt < 2; mt++) {
            const int ma = m0 + wm * 32 + mt * 16 + cg;
            float* pa = C + (size_t)ma * DD + nb;
            float* pb = C + (size_t)(ma + 8) * DD + nb;
            #pragma unroll
            for (int nt = 0; nt < 4; nt++) {
                const int cc = nt * 8 + ctg * 2;
                float2 bv = *(const float2*)(bias + nb + cc);
                *(float2*)(pa + cc) =
                    make_float2(acc[mt][nt][0] + bv.x, acc[mt][nt][1] + bv.y);
                *(float2*)(pb + cc) =
                    make_float2(acc[mt][nt][2] + bv.x, acc[mt][nt][3] + bv.y);
            }
        }
    }
}

// ---------------------------------------------------------------------------
// Flash attention, fp16 single-product mma.sync. 128-query CTA tile,
// 8 warps x 16 rows, key tiles of 64, 3-stage cp.async K/V pipeline.
// smem: Q 0..16K, P 16K..32K, stage st at 32K + st*16K (K 8K, V 8K). 80KB.
// ---------------------------------------------------------------------------
__global__ __launch_bounds__(256, 2)
void attn_mma_kernel()
{
    extern __shared__ char smem[];
    const uint32_t sm0 = smem_to_u32(smem);

    const int tid = threadIdx.x;
    const int w = tid >> 5, lane = tid & 31;
    const int bh = blockIdx.y;
    const int q0 = blockIdx.x * 128;

    const size_t bho = (size_t)bh * SS * HDIM;
    const char* qsrc = (const char*)(g_qf + bho + (size_t)q0 * HDIM);
    const char* ksrc = (const char*)(g_kf + bho);
    const char* vsrc = (const char*)(g_vf + bho);

    auto load_kv = [&](int stage, int kt) {
        const uint32_t sb = sm0 + 32768 + stage * 16384;
        const size_t roff = (size_t)(kt * 64) * 128;   // bytes
        #pragma unroll
        for (int j = 0; j < 2; j++) {
            const int g = tid + j * 256;               // 512 granules per tile
            const int r = g >> 3;
            const uint32_t cb = (uint32_t)((g & 7) * 16);
            const uint32_t so = SWZ128((uint32_t)(r * 128) + cb);
            CP_ASYNC16(sb + so,        ksrc + roff + (size_t)r * 128 + cb);
            CP_ASYNC16(sb + 8192 + so, vsrc + roff + (size_t)r * 128 + cb);
        }
    };

    // group 0: Q tile (128 rows x 128B) + KV stage 0
    #pragma unroll
    for (int j = 0; j < 4; j++) {
        const int g = tid + j * 256;                   // 1024 granules
        const int r = g >> 3;
        const uint32_t cb = (uint32_t)((g & 7) * 16);
        CP_ASYNC16(sm0 + SWZ128((uint32_t)(r * 128) + cb),
                   qsrc + (size_t)r * 128 + cb);
    }
    load_kv(0, 0);
    CP_COMMIT();
    load_kv(1, 1);
    CP_COMMIT();
    load_kv(2, 2);
    CP_COMMIT();

    const int sub   = lane >> 3;
    const int a_rin = (lane & 7) + (sub & 1) * 8;
    const int a_kh  = sub >> 1;
    const int b_nt  = sub >> 1;
    const int b_kh  = sub & 1;
    const int b_row = lane & 7;
    const int v_row = lane & 15;
    const int v_col = (lane >> 4) * 8;
    const int cg = lane >> 2, ctg = lane & 3;

    float acc_o[8][4] = {};
    float mi0 = -1e30f, mi1 = -1e30f, li0 = 0.f, li1 = 0.f;

    const int KT = SS / 64;  // 32
    for (int kt = 0; kt < KT; kt++) {
        const int stage = kt % 3;
        if (kt <= KT - 3)      { CP_WAIT2(); }
        else if (kt == KT - 2) { CP_WAIT1(); }
        else                   { CP_WAIT0(); }
        __syncthreads();

        const uint32_t Kb = sm0 + 32768 + stage * 16384;
        const uint32_t Vb = Kb + 8192;

        // ---- S = Q K^T (single fp16 product) ----
        float acc_s[8][4] = {};
        #pragma unroll
        for (int ks = 0; ks < 4; ks++) {
            uint32_t ah[4];
            const uint32_t offa =
                SWZ128((uint32_t)((w * 16 + a_rin) * 128 + (ks * 2 + a_kh) * 16));
            ldsm_x4(ah[0], ah[1], ah[2], ah[3], sm0 + offa);
            #pragma unroll
            for (int pr = 0; pr < 4; pr++) {
                const uint32_t offb =
                    SWZ128((uint32_t)((pr * 16 + b_nt * 8 + b_row) * 128 + (ks * 2 + b_kh) * 16));
                uint32_t r0, r1, r2, r3;
                ldsm_x4(r0, r1, r2, r3, Kb + offb);
                uint32_t b0[2] = {r0, r1}, b1[2] = {r2, r3};
                mma16816h(acc_s[2 * pr],     ah, b0);
                mma16816h(acc_s[2 * pr + 1], ah, b1);
            }
        }

        // ---- online softmax (rows cg, cg+8; quad shfl reductions) ----
        float t0 = -1e30f, t1 = -1e30f;
        #pragma unroll
        for (int nt = 0; nt < 8; nt++) {
            t0 = fmaxf(t0, fmaxf(acc_s[nt][0], acc_s[nt][1]));
            t1 = fmaxf(t1, fmaxf(acc_s[nt][2], acc_s[nt][3]));
        }
        t0 = fmaxf(t0, __shfl_xor_sync(0xffffffffu, t0, 1));
        t0 = fmaxf(t0, __shfl_xor_sync(0xffffffffu, t0, 2));
        t1 = fmaxf(t1, __shfl_xor_sync(0xffffffffu, t1, 1));
        t1 = fmaxf(t1, __shfl_xor_sync(0xffffffffu, t1, 2));
        const float mn0 = fmaxf(mi0, t0 * ATT_SCALE);
        const float mn1 = fmaxf(mi1, t1 * ATT_SCALE);
        const float c0 = __expf(mi0 - mn0), c1 = __expf(mi1 - mn1);
        float rs0 = 0.f, rs1 = 0.f;
        #pragma unroll
        for (int nt = 0; nt < 8; nt++) {
            float p;
            p = __expf(acc_s[nt][0] * ATT_SCALE - mn0); acc_s[nt][0] = p; rs0 += p;
            p = __expf(acc_s[nt][1] * ATT_SCALE - mn0); acc_s[nt][1] = p; rs0 += p;
            p = __expf(acc_s[nt][2] * ATT_SCALE - mn1); acc_s[nt][2] = p; rs1 += p;
            p = __expf(acc_s[nt][3] * ATT_SCALE - mn1); acc_s[nt][3] = p; rs1 += p;
        }
        rs0 += __shfl_xor_sync(0xffffffffu, rs0, 1);
        rs0 += __shfl_xor_sync(0xffffffffu, rs0, 2);
        rs1 += __shfl_xor_sync(0xffffffffu, rs1, 1);
        rs1 += __shfl_xor_sync(0xffffffffu, rs1, 2);
        li0 = li0 * c0 + rs0;  li1 = li1 * c1 + rs1;
        mi0 = mn0;  mi1 = mn1;
        #pragma unroll
        for (int nt = 0; nt < 8; nt++) {
            acc_o[nt][0] *= c0; acc_o[nt][1] *= c0;
            acc_o[nt][2] *= c1; acc_o[nt][3] *= c1;
        }

        // ---- write P as fp16 to smem ----
        #pragma unroll
        for (int nt = 0; nt < 8; nt++) {
            const uint32_t off0 =
                SWZ128((uint32_t)((w * 16 + cg) * 128 + (nt * 8 + ctg * 2) * 2));
            *(uint32_t*)(smem + 16384 + off0) = pack_h2(acc_s[nt][0], acc_s[nt][1]);
            const uint32_t off1 =
                SWZ128((uint32_t)((w * 16 + cg + 8) * 128 + (nt * 8 + ctg * 2) * 2));
            *(uint32_t*)(smem + 16384 + off1) = pack_h2(acc_s[nt][2], acc_s[nt][3]);
        }
        __syncthreads();

        // ---- O += P V (fp16 single product; V via ldmatrix.trans) ----
        #pragma unroll
        for (int ks = 0; ks < 4; ks++) {
            uint32_t ah[4];
            const uint32_t offa =
                SWZ128((uint32_t)((w * 16 + a_rin) * 128 + (ks * 2 + a_kh) * 16));
            ldsm_x4(ah[0], ah[1], ah[2], ah[3], sm0 + 16384 + offa);
            #pragma unroll
            for (int pr = 0; pr < 4; pr++) {
                const uint32_t offv =
                    SWZ128((uint32_t)((ks * 16 + v_row) * 128 + (pr * 16 + v_col) * 2));
                uint32_t r0, r1, r2, r3;
                ldsm_x4_t(r0, r1, r2, r3, Vb + offv);
                uint32_t b0[2] = {r0, r1}, b1[2] = {r2, r3};
                mma16816h(acc_o[2 * pr],     ah, b0);
                mma16816h(acc_o[2 * pr + 1], ah, b1);
            }
        }
        __syncthreads();   // all warps done with this stage's K/V before refill

        if (kt + 3 < KT) {
            load_kv(stage, kt + 3);
            CP_COMMIT();
        }
    }

    // ---- epilogue: normalize, split hi/lo bf16, write to g_ao{h,l} ----
    const int b = bh >> 4, hd = bh & 15;
    const float inv0 = 1.0f / li0, inv1 = 1.0f / li1;
    const int r0 = q0 + w * 16 + cg, r1 = r0 + 8;
    const size_t base0 = ((size_t)(b * SS + r0)) * DD + hd * HDIM;
    const size_t base1 = ((size_t)(b * SS + r1)) * DD + hd * HDIM;
    #pragma unroll
    for (int nt = 0; nt < 8; nt++) {
        const int cc = nt * 8 + ctg * 2;
        uint32_t lo, hi;
        hi = pack_split(acc_o[nt][0] * inv0, acc_o[nt][1] * inv0, lo);
        *(uint32_t*)(g_aoh + base0 + cc) = hi;
        *(uint32_t*)(g_aol + base0 + cc) = lo;
        hi = pack_split(acc_o[nt][2] * inv1, acc_o[nt][3] * inv1, lo);
        *(uint32_t*)(g_aoh + base1 + cc) = hi;
        *(uint32_t*)(g_aol + base1 + cc) = lo;
    }
}

// ---------------------------------------------------------------------------
extern "C" void kernel_launch(void* const* d_in, const int* in_sizes, int n_in,
                              void* d_out, int out_size)
{
    const float* x     = (const float*)d_in[0];
    const float* W_qkv = (const float*)d_in[1];
    const float* b_qkv = (const float*)d_in[2];
    const float* W_out = (const float*)d_in[3];
    const float* b_out = (const float*)d_in[4];
    float* out = (float*)d_out;

    const int gemm_smem = 3 * 4 * 16384;           // 196608 (3 stages)
    const int attn_smem = 2 * 16384 + 3 * 16384;   // 81920
    cudaFuncSetAttribute(mma_gemm<true>,
                         cudaFuncAttributeMaxDynamicSharedMemorySize, gemm_smem);
    cudaFuncSetAttribute(mma_gemm<false>,
                         cudaFuncAttributeMaxDynamicSharedMemorySize, gemm_smem);
    cudaFuncSetAttribute(attn_mma_kernel,
                         cudaFuncAttributeMaxDynamicSharedMemorySize, attn_smem);

    __nv_bfloat16 *xh, *xl, *wqh, *wql, *woh, *wol, *aoh, *aol;
    cudaGetSymbolAddress((void**)&xh,  g_xh);
    cudaGetSymbolAddress((void**)&xl,  g_xl);
    cudaGetSymbolAddress((void**)&wqh, g_wqkvh);
    cudaGetSymbolAddress((void**)&wql, g_wqkvl);
    cudaGetSymbolAddress((void**)&woh, g_wouth);
    cudaGetSymbolAddress((void**)&wol, g_woutl);
    cudaGetSymbolAddress((void**)&aoh, g_aoh);
    cudaGetSymbolAddress((void**)&aol, g_aol);

    // 0) prep: split x, transpose+split weights
    split_kernel<<<(M_TOT * DD / 4) / 256, 256>>>(
        (const float4*)x, (uint2*)xh, (uint2*)xl);
    transpose_split_kernel<<<dim3(N_QKV / 32, DD / 32), 256>>>(W_qkv, wqh, wql, N_QKV);
    transpose_split_kernel<<<dim3(DD / 32, DD / 32), 256>>>(W_out, woh, wol, DD);

    // 1) QKV projection (3-product bf16) -> fp16 Q,K,V in [B,H,S,HD]
    mma_gemm<true><<<dim3(N_QKV / 128, M_TOT / 128), 512, gemm_smem>>>(
        xh, xl, wqh, wql, b_qkv, nullptr);

    // 2) flash attention (fp16 single-product mma.sync) -> bf16 hi/lo ao
    attn_mma_kernel<<<dim3(SS / 128, BB * HH), 256, attn_smem>>>();

    // 3) output projection (3-product bf16, fp32 out)
    mma_gemm<false><<<dim3(DD / 128, M_TOT / 128), 512, gemm_smem>>>(
        aoh, aol, woh, wol, b_out, out);
}

// round 11
// speedup vs baseline: 5.8288x; 1.1996x over previous
#include <cuda_runtime.h>
#include <cuda_bf16.h>
#include <cuda_fp16.h>
#include <cstdint>

#define DD 1024
#define HH 16
#define HDIM 64
#define BB 2
#define SS 2048
#define M_TOT (BB*SS)      // 4096
#define N_QKV (3*DD)       // 3072

// ---------------------------------------------------------------------------
// scratch (allocation-free rule: device globals)
// ---------------------------------------------------------------------------
__device__ __align__(256) __half g_qf[BB*HH*SS*HDIM];   // [B,H,S,HD] fp16 (pre-scaled by 1/8)
__device__ __align__(256) __half g_kf[BB*HH*SS*HDIM];
__device__ __align__(256) __half g_vf[BB*HH*SS*HDIM];

__device__ __align__(256) __half g_xh[(size_t)M_TOT*DD];     // x hi/lo fp16
__device__ __align__(256) __half g_xl[(size_t)M_TOT*DD];
__device__ __align__(256) __half g_wqkvf[(size_t)N_QKV*DD];  // W^T [N][K] fp16
__device__ __align__(256) __half g_woutf[(size_t)DD*DD];
__device__ __align__(256) __half g_aoh[(size_t)M_TOT*DD];    // attn out hi/lo fp16
__device__ __align__(256) __half g_aol[(size_t)M_TOT*DD];

// ---------------------------------------------------------------------------
// PTX helpers (base sm_80 ISA — harness lowers through compute_103)
// ---------------------------------------------------------------------------
__device__ __forceinline__ uint32_t smem_to_u32(const void* p) {
    uint32_t a;
    asm("{ .reg .u64 t; cvta.to.shared.u64 t, %1; cvt.u32.u64 %0, t; }"
        : "=r"(a) : "l"(p));
    return a;
}
#define CP_ASYNC16(sm, gp) \
    asm volatile("cp.async.cg.shared.global [%0], [%1], 16;" :: "r"(sm), "l"(gp) : "memory")
#define CP_COMMIT() asm volatile("cp.async.commit_group;" ::: "memory")
#define CP_WAIT2()  asm volatile("cp.async.wait_group 2;" ::: "memory")
#define CP_WAIT1()  asm volatile("cp.async.wait_group 1;" ::: "memory")
#define CP_WAIT0()  asm volatile("cp.async.wait_group 0;" ::: "memory")

#define SWZ128(o) ((o) ^ (((o) >> 3) & 0x70))

__device__ __forceinline__ void ldsm_x4(uint32_t& r0, uint32_t& r1,
                                        uint32_t& r2, uint32_t& r3, uint32_t a) {
    asm volatile("ldmatrix.sync.aligned.m8n8.x4.shared.b16 {%0,%1,%2,%3}, [%4];"
                 : "=r"(r0), "=r"(r1), "=r"(r2), "=r"(r3) : "r"(a));
}
__device__ __forceinline__ void ldsm_x4_t(uint32_t& r0, uint32_t& r1,
                                          uint32_t& r2, uint32_t& r3, uint32_t a) {
    asm volatile("ldmatrix.sync.aligned.m8n8.x4.trans.shared.b16 {%0,%1,%2,%3}, [%4];"
                 : "=r"(r0), "=r"(r1), "=r"(r2), "=r"(r3) : "r"(a));
}
__device__ __forceinline__ void mma16816h(float* c, const uint32_t* a,
                                          const uint32_t* b) {
    asm volatile(
        "mma.sync.aligned.m16n8k16.row.col.f32.f16.f16.f32 "
        "{%0,%1,%2,%3}, {%4,%5,%6,%7}, {%8,%9}, {%0,%1,%2,%3};"
        : "+f"(c[0]), "+f"(c[1]), "+f"(c[2]), "+f"(c[3])
        : "r"(a[0]), "r"(a[1]), "r"(a[2]), "r"(a[3]), "r"(b[0]), "r"(b[1]));
}
// pack two fp32 -> half2 (lo = v0, hi = v1)
__device__ __forceinline__ uint32_t pack_h2(float v0, float v1) {
    uint32_t r;
    asm("cvt.rn.f16x2.f32 %0, %1, %2;" : "=r"(r) : "f"(v1), "f"(v0));
    return r;
}
// split fp32 pair -> packed fp16 hi pair (ret) and fp16 lo pair (out param)
__device__ __forceinline__ uint32_t pack_split_h(float v0, float v1, uint32_t& lo) {
    __half h0 = __float2half(v0), h1 = __float2half(v1);
    __half l0 = __float2half(v0 - __half2float(h0));
    __half l1 = __float2half(v1 - __half2float(h1));
    lo = (uint32_t)__half_as_ushort(l0) | ((uint32_t)__half_as_ushort(l1) << 16);
    return (uint32_t)__half_as_ushort(h0) | ((uint32_t)__half_as_ushort(h1) << 16);
}

// ---------------------------------------------------------------------------
// prep kernels
// ---------------------------------------------------------------------------
// x fp32 -> fp16 hi + fp16 lo (residual)
__global__ __launch_bounds__(256) void split_f16_kernel(
    const float4* __restrict__ in, uint2* __restrict__ hi, uint2* __restrict__ lo)
{
    int i = blockIdx.x * blockDim.x + threadIdx.x;
    float4 v = in[i];
    float vv[4] = {v.x, v.y, v.z, v.w};
    __half h[4], l[4];
    #pragma unroll
    for (int j = 0; j < 4; j++) {
        h[j] = __float2half(vv[j]);
        l[j] = __float2half(vv[j] - __half2float(h[j]));
    }
    hi[i] = *(uint2*)h;
    lo[i] = *(uint2*)l;
}

// W[K][N] fp32 -> W^T [N][K=1024] fp16
__global__ __launch_bounds__(256) void transpose_f16_kernel(
    const float* __restrict__ W, __half* __restrict__ T, int N)
{
    __shared__ float t[32][33];
    const int k0 = blockIdx.y * 32, n0 = blockIdx.x * 32;
    const int tx = threadIdx.x & 31, ty = threadIdx.x >> 5;
    #pragma unroll
    for (int j = 0; j < 4; j++)
        t[ty + j * 8][tx] = W[(size_t)(k0 + ty + j * 8) * N + n0 + tx];
    __syncthreads();
    #pragma unroll
    for (int j = 0; j < 4; j++) {
        const int n = n0 + ty + j * 8;
        T[(size_t)n * DD + k0 + tx] = __float2half(t[tx][ty + j * 8]);
    }
}

// ---------------------------------------------------------------------------
// mma.sync 2-product fp16 GEMM: C = (Ah+Al)[M,1024] @ W_fp16 + bias.
// 512 threads (16 warps, 32x32 warp tiles), 128x128 CTA tile, K chunks of 64,
// 3-stage cp.async pipeline, 3 smem tiles/stage (Ah, Al, B).
// QKV=true: result -> fp16, scattered to g_{q,k,v}f ([B,H,S,HD]); Q pre-scaled 1/8.
// ---------------------------------------------------------------------------
template<bool QKV>
__global__ __launch_bounds__(512)
void mma_gemm(const __half* __restrict__ Ah,
              const __half* __restrict__ Al,
              const __half* __restrict__ B,
              const float* __restrict__ bias,
              float* __restrict__ C)
{
    extern __shared__ char smem[];
    const uint32_t sm0 = smem_to_u32(smem);   // stage s: +s*49152, tile t: +t*16384

    const int tid = threadIdx.x;
    const int wid = tid >> 5, lane = tid & 31;
    const int m0 = blockIdx.y * 128, n0 = blockIdx.x * 128;
    const int wm = wid & 3;     // 4 row groups of 32
    const int wn = wid >> 2;    // 4 col groups of 32

    const char* srcs[3] = {
        (const char*)(Ah + (size_t)m0 * DD),
        (const char*)(Al + (size_t)m0 * DD),
        (const char*)(B  + (size_t)n0 * DD)
    };

    auto load_stage = [&](int stage, int chunk) {
        const uint32_t sbase = sm0 + stage * 49152;
        const size_t coff = (size_t)chunk * 128;
        #pragma unroll
        for (int t = 0; t < 3; t++) {
            const uint32_t tb = sbase + t * 16384;
            #pragma unroll
            for (int j = 0; j < 2; j++) {
                const int g = tid + j * 512;          // 1024 granules of 16B
                const int r = g >> 3;
                const uint32_t cb = (uint32_t)((g & 7) * 16);
                CP_ASYNC16(tb + SWZ128((uint32_t)(r * 128) + cb),
                           srcs[t] + (size_t)r * (DD * 2) + coff + cb);
            }
        }
        CP_COMMIT();
    };

    load_stage(0, 0);
    load_stage(1, 1);
    load_stage(2, 2);

    float acc[2][4][4] = {};

    const int sub   = lane >> 3;
    const int a_rin = (lane & 7) + (sub & 1) * 8;
    const int a_kh  = sub >> 1;
    const int b_nt  = sub >> 1;
    const int b_kh  = sub & 1;
    const int b_row = lane & 7;

    const int K_CHUNKS = DD / 64;  // 16
    for (int i = 0; i < K_CHUNKS; i++) {
        const int stage = i % 3;
        if (i <= K_CHUNKS - 3)      { CP_WAIT2(); }
        else if (i == K_CHUNKS - 2) { CP_WAIT1(); }
        else                        { CP_WAIT0(); }
        __syncthreads();

        const uint32_t sb  = sm0 + stage * 49152;
        const uint32_t Ahb = sb, Alb = sb + 16384, Bb = sb + 32768;

        #pragma unroll
        for (int ks = 0; ks < 4; ks++) {
            uint32_t ahf[2][4], alf[2][4], bf[4][2];
            const uint32_t gka = (uint32_t)((ks * 2 + a_kh) * 16);
            #pragma unroll
            for (int mt = 0; mt < 2; mt++) {
                const uint32_t off =
                    SWZ128((uint32_t)((wm * 32 + mt * 16 + a_rin) * 128) + gka);
                ldsm_x4(ahf[mt][0], ahf[mt][1], ahf[mt][2], ahf[mt][3], Ahb + off);
                ldsm_x4(alf[mt][0], alf[mt][1], alf[mt][2], alf[mt][3], Alb + off);
            }
            const uint32_t gkb = (uint32_t)((ks * 2 + b_kh) * 16);
            #pragma unroll
            for (int pr = 0; pr < 2; pr++) {
                const uint32_t off =
                    SWZ128((uint32_t)((wn * 32 + pr * 16 + b_nt * 8 + b_row) * 128) + gkb);
                uint32_t r0, r1, r2, r3;
                ldsm_x4(r0, r1, r2, r3, Bb + off);
                bf[pr * 2][0] = r0; bf[pr * 2][1] = r1;
                bf[pr * 2 + 1][0] = r2; bf[pr * 2 + 1][1] = r3;
            }
            #pragma unroll
            for (int mt = 0; mt < 2; mt++)
                #pragma unroll
                for (int nt = 0; nt < 4; nt++) {
                    mma16816h(acc[mt][nt], ahf[mt], bf[nt]);
                    mma16816h(acc[mt][nt], alf[mt], bf[nt]);
                }
        }
        __syncthreads();
        if (i + 3 < K_CHUNKS) load_stage(stage, i + 3);
    }

    const int cg = lane >> 2, ctg = lane & 3;
    const int nb = n0 + wn * 32;

    if (QKV) {
        const int tsel = nb >> 10;
        const int h = (nb & 1023) >> 6;
        const int db = nb & 63;
        __half* dst = (tsel == 0) ? g_qf : (tsel == 1) ? g_kf : g_vf;
        const float sc = (tsel == 0) ? 0.125f : 1.0f;   // fold 1/sqrt(HD) into Q (exact)
        #pragma unroll
        for (int mt = 0; mt < 2; mt++) {
            const int ma = m0 + wm * 32 + mt * 16 + cg;
            const int mb = ma + 8;
            const int ba = ma >> 11, sa = ma & 2047;
            const int bb = mb >> 11, sbb = mb & 2047;
            const size_t ra = (((size_t)(ba * HH + h)) * SS + sa) * HDIM + db;
            const size_t rb = (((size_t)(bb * HH + h)) * SS + sbb) * HDIM + db;
            #pragma unroll
            for (int nt = 0; nt < 4; nt++) {
                const int cc = nt * 8 + ctg * 2;
                float2 bv = *(const float2*)(bias + nb + cc);
                *(uint32_t*)(dst + ra + cc) =
                    pack_h2((acc[mt][nt][0] + bv.x) * sc, (acc[mt][nt][1] + bv.y) * sc);
                *(uint32_t*)(dst + rb + cc) =
                    pack_h2((acc[mt][nt][2] + bv.x) * sc, (acc[mt][nt][3] + bv.y) * sc);
            }
        }
    } else {
        #pragma unroll
        for (int mt = 0; mt < 2; mt++) {
            const int ma = m0 + wm * 32 + mt * 16 + cg;
            float* pa = C + (size_t)ma * DD + nb;
            float* pb = C + (size_t)(ma + 8) * DD + nb;
            #pragma unroll
            for (int nt = 0; nt < 4; nt++) {
                const int cc = nt * 8 + ctg * 2;
                float2 bv = *(const float2*)(bias + nb + cc);
                *(float2*)(pa + cc) =
                    make_float2(acc[mt][nt][0] + bv.x, acc[mt][nt][1] + bv.y);
                *(float2*)(pb + cc) =
                    make_float2(acc[mt][nt][2] + bv.x, acc[mt][nt][3] + bv.y);
            }
        }
    }
}

// ---------------------------------------------------------------------------
// Flash attention, fp16 single-product mma.sync. 128-query CTA tile,
// 8 warps x 16 rows, key tiles of 64, 3-stage cp.async K/V pipeline.
// Q pre-scaled by 1/8 at the QKV epilogue -> raw scores used directly.
// smem: Q 0..16K, P 16K..32K, stage st at 32K + st*16K (K 8K, V 8K). 80KB.
// ---------------------------------------------------------------------------
__global__ __launch_bounds__(256, 2)
void attn_mma_kernel()
{
    extern __shared__ char smem[];
    const uint32_t sm0 = smem_to_u32(smem);

    const int tid = threadIdx.x;
    const int w = tid >> 5, lane = tid & 31;
    const int bh = blockIdx.y;
    const int q0 = blockIdx.x * 128;

    const size_t bho = (size_t)bh * SS * HDIM;
    const char* qsrc = (const char*)(g_qf + bho + (size_t)q0 * HDIM);
    const char* ksrc = (const char*)(g_kf + bho);
    const char* vsrc = (const char*)(g_vf + bho);

    auto load_kv = [&](int stage, int kt) {
        const uint32_t sb = sm0 + 32768 + stage * 16384;
        const size_t roff = (size_t)(kt * 64) * 128;   // bytes
        #pragma unroll
        for (int j = 0; j < 2; j++) {
            const int g = tid + j * 256;               // 512 granules per tile
            const int r = g >> 3;
            const uint32_t cb = (uint32_t)((g & 7) * 16);
            const uint32_t so = SWZ128((uint32_t)(r * 128) + cb);
            CP_ASYNC16(sb + so,        ksrc + roff + (size_t)r * 128 + cb);
            CP_ASYNC16(sb + 8192 + so, vsrc + roff + (size_t)r * 128 + cb);
        }
    };

    // group 0: Q tile (128 rows x 128B) + KV stage 0
    #pragma unroll
    for (int j = 0; j < 4; j++) {
        const int g = tid + j * 256;                   // 1024 granules
        const int r = g >> 3;
        const uint32_t cb = (uint32_t)((g & 7) * 16);
        CP_ASYNC16(sm0 + SWZ128((uint32_t)(r * 128) + cb),
                   qsrc + (size_t)r * 128 + cb);
    }
    load_kv(0, 0);
    CP_COMMIT();
    load_kv(1, 1);
    CP_COMMIT();
    load_kv(2, 2);
    CP_COMMIT();

    const int sub   = lane >> 3;
    const int a_rin = (lane & 7) + (sub & 1) * 8;
    const int a_kh  = sub >> 1;
    const int b_nt  = sub >> 1;
    const int b_kh  = sub & 1;
    const int b_row = lane & 7;
    const int v_row = lane & 15;
    const int v_col = (lane >> 4) * 8;
    const int cg = lane >> 2, ctg = lane & 3;

    float acc_o[8][4] = {};
    float mi0 = -1e30f, mi1 = -1e30f, li0 = 0.f, li1 = 0.f;

    const int KT = SS / 64;  // 32
    for (int kt = 0; kt < KT; kt++) {
        const int stage = kt % 3;
        if (kt <= KT - 3)      { CP_WAIT2(); }
        else if (kt == KT - 2) { CP_WAIT1(); }
        else                   { CP_WAIT0(); }
        __syncthreads();

        const uint32_t Kb = sm0 + 32768 + stage * 16384;
        const uint32_t Vb = Kb + 8192;

        // ---- S = Q K^T (single fp16 product; Q pre-scaled) ----
        float acc_s[8][4] = {};
        #pragma unroll
        for (int ks = 0; ks < 4; ks++) {
            uint32_t ah[4];
            const uint32_t offa =
                SWZ128((uint32_t)((w * 16 + a_rin) * 128 + (ks * 2 + a_kh) * 16));
            ldsm_x4(ah[0], ah[1], ah[2], ah[3], sm0 + offa);
            #pragma unroll
            for (int pr = 0; pr < 4; pr++) {
                const uint32_t offb =
                    SWZ128((uint32_t)((pr * 16 + b_nt * 8 + b_row) * 128 + (ks * 2 + b_kh) * 16));
                uint32_t r0, r1, r2, r3;
                ldsm_x4(r0, r1, r2, r3, Kb + offb);
                uint32_t b0[2] = {r0, r1}, b1[2] = {r2, r3};
                mma16816h(acc_s[2 * pr],     ah, b0);
                mma16816h(acc_s[2 * pr + 1], ah, b1);
            }
        }

        // ---- online softmax (rows cg, cg+8; quad shfl reductions) ----
        float t0 = -1e30f, t1 = -1e30f;
        #pragma unroll
        for (int nt = 0; nt < 8; nt++) {
            t0 = fmaxf(t0, fmaxf(acc_s[nt][0], acc_s[nt][1]));
            t1 = fmaxf(t1, fmaxf(acc_s[nt][2], acc_s[nt][3]));
        }
        t0 = fmaxf(t0, __shfl_xor_sync(0xffffffffu, t0, 1));
        t0 = fmaxf(t0, __shfl_xor_sync(0xffffffffu, t0, 2));
        t1 = fmaxf(t1, __shfl_xor_sync(0xffffffffu, t1, 1));
        t1 = fmaxf(t1, __shfl_xor_sync(0xffffffffu, t1, 2));
        const float mn0 = fmaxf(mi0, t0);
        const float mn1 = fmaxf(mi1, t1);
        const float c0 = __expf(mi0 - mn0), c1 = __expf(mi1 - mn1);
        float rs0 = 0.f, rs1 = 0.f;
        #pragma unroll
        for (int nt = 0; nt < 8; nt++) {
            float p;
            p = __expf(acc_s[nt][0] - mn0); acc_s[nt][0] = p; rs0 += p;
            p = __expf(acc_s[nt][1] - mn0); acc_s[nt][1] = p; rs0 += p;
            p = __expf(acc_s[nt][2] - mn1); acc_s[nt][2] = p; rs1 += p;
            p = __expf(acc_s[nt][3] - mn1); acc_s[nt][3] = p; rs1 += p;
        }
        rs0 += __shfl_xor_sync(0xffffffffu, rs0, 1);
        rs0 += __shfl_xor_sync(0xffffffffu, rs0, 2);
        rs1 += __shfl_xor_sync(0xffffffffu, rs1, 1);
        rs1 += __shfl_xor_sync(0xffffffffu, rs1, 2);
        li0 = li0 * c0 + rs0;  li1 = li1 * c1 + rs1;
        mi0 = mn0;  mi1 = mn1;
        #pragma unroll
        for (int nt = 0; nt < 8; nt++) {
            acc_o[nt][0] *= c0; acc_o[nt][1] *= c0;
            acc_o[nt][2] *= c1; acc_o[nt][3] *= c1;
        }

        // ---- write P as fp16 to smem ----
        #pragma unroll
        for (int nt = 0; nt < 8; nt++) {
            const uint32_t off0 =
                SWZ128((uint32_t)((w * 16 + cg) * 128 + (nt * 8 + ctg * 2) * 2));
            *(uint32_t*)(smem + 16384 + off0) = pack_h2(acc_s[nt][0], acc_s[nt][1]);
            const uint32_t off1 =
                SWZ128((uint32_t)((w * 16 + cg + 8) * 128 + (nt * 8 + ctg * 2) * 2));
            *(uint32_t*)(smem + 16384 + off1) = pack_h2(acc_s[nt][2], acc_s[nt][3]);
        }
        __syncthreads();

        // ---- O += P V (fp16 single product; V via ldmatrix.trans) ----
        #pragma unroll
        for (int ks = 0; ks < 4; ks++) {
            uint32_t ah[4];
            const uint32_t offa =
                SWZ128((uint32_t)((w * 16 + a_rin) * 128 + (ks * 2 + a_kh) * 16));
            ldsm_x4(ah[0], ah[1], ah[2], ah[3], sm0 + 16384 + offa);
            #pragma unroll
            for (int pr = 0; pr < 4; pr++) {
                const uint32_t offv =
                    SWZ128((uint32_t)((ks * 16 + v_row) * 128 + (pr * 16 + v_col) * 2));
                uint32_t r0, r1, r2, r3;
                ldsm_x4_t(r0, r1, r2, r3, Vb + offv);
                uint32_t b0[2] = {r0, r1}, b1[2] = {r2, r3};
                mma16816h(acc_o[2 * pr],     ah, b0);
                mma16816h(acc_o[2 * pr + 1], ah, b1);
            }
        }
        __syncthreads();   // all warps done with this stage's K/V before refill

        if (kt + 3 < KT) {
            load_kv(stage, kt + 3);
            CP_COMMIT();
        }
    }

    // ---- epilogue: normalize, split fp16 hi/lo, write to g_ao{h,l} ----
    const int b = bh >> 4, hd = bh & 15;
    const float inv0 = 1.0f / li0, inv1 = 1.0f / li1;
    const int r0 = q0 + w * 16 + cg, r1 = r0 + 8;
    const size_t base0 = ((size_t)(b * SS + r0)) * DD + hd * HDIM;
    const size_t base1 = ((size_t)(b * SS + r1)) * DD + hd * HDIM;
    #pragma unroll
    for (int nt = 0; nt < 8; nt++) {
        const int cc = nt * 8 + ctg * 2;
        uint32_t lo, hi;
        hi = pack_split_h(acc_o[nt][0] * inv0, acc_o[nt][1] * inv0, lo);
        *(uint32_t*)(g_aoh + base0 + cc) = hi;
        *(uint32_t*)(g_aol + base0 + cc) = lo;
        hi = pack_split_h(acc_o[nt][2] * inv1, acc_o[nt][3] * inv1, lo);
        *(uint32_t*)(g_aoh + base1 + cc) = hi;
        *(uint32_t*)(g_aol + base1 + cc) = lo;
    }
}

// ---------------------------------------------------------------------------
extern "C" void kernel_launch(void* const* d_in, const int* in_sizes, int n_in,
                              void* d_out, int out_size)
{
    const float* x     = (const float*)d_in[0];
    const float* W_qkv = (const float*)d_in[1];
    const float* b_qkv = (const float*)d_in[2];
    const float* W_out = (const float*)d_in[3];
    const float* b_out = (const float*)d_in[4];
    float* out = (float*)d_out;

    const int gemm_smem = 3 * 3 * 16384;           // 147456 (3 stages x 3 tiles)
    const int attn_smem = 2 * 16384 + 3 * 16384;   // 81920
    cudaFuncSetAttribute(mma_gemm<true>,
                         cudaFuncAttributeMaxDynamicSharedMemorySize, gemm_smem);
    cudaFuncSetAttribute(mma_gemm<false>,
                         cudaFuncAttributeMaxDynamicSharedMemorySize, gemm_smem);
    cudaFuncSetAttribute(attn_mma_kernel,
                         cudaFuncAttributeMaxDynamicSharedMemorySize, attn_smem);

    __half *xh, *xl, *wq, *wo, *aoh, *aol;
    cudaGetSymbolAddress((void**)&xh,  g_xh);
    cudaGetSymbolAddress((void**)&xl,  g_xl);
    cudaGetSymbolAddress((void**)&wq,  g_wqkvf);
    cudaGetSymbolAddress((void**)&wo,  g_woutf);
    cudaGetSymbolAddress((void**)&aoh, g_aoh);
    cudaGetSymbolAddress((void**)&aol, g_aol);

    // 0) prep: split x (fp16 hi/lo), transpose weights to fp16 [N][K]
    split_f16_kernel<<<(M_TOT * DD / 4) / 256, 256>>>(
        (const float4*)x, (uint2*)xh, (uint2*)xl);
    transpose_f16_kernel<<<dim3(N_QKV / 32, DD / 32), 256>>>(W_qkv, wq, N_QKV);
    transpose_f16_kernel<<<dim3(DD / 32, DD / 32), 256>>>(W_out, wo, DD);

    // 1) QKV projection (2-product fp16) -> fp16 Q(pre-scaled),K,V in [B,H,S,HD]
    mma_gemm<true><<<dim3(N_QKV / 128, M_TOT / 128), 512, gemm_smem>>>(
        xh, xl, wq, b_qkv, nullptr);

    // 2) flash attention (fp16 single-product mma.sync) -> fp16 hi/lo ao
    attn_mma_kernel<<<dim3(SS / 128, BB * HH), 256, attn_smem>>>();

    // 3) output projection (2-product fp16, fp32 out)
    mma_gemm<false><<<dim3(DD / 128, M_TOT / 128), 512, gemm_smem>>>(
        aoh, aol, wo, b_out, out);
}

// round 12
// speedup vs baseline: 7.9436x; 1.3628x over previous
#include <cuda_runtime.h>
#include <cuda_fp16.h>
#include <cstdint>

#define DD 1024
#define HH 16
#define HDIM 64
#define BB 2
#define SS 2048
#define M_TOT (BB*SS)      // 4096
#define N_QKV (3*DD)       // 3072

// ---------------------------------------------------------------------------
// scratch (allocation-free rule: device globals) — all single fp16 now
// ---------------------------------------------------------------------------
__device__ __align__(256) __half g_qf[BB*HH*SS*HDIM];   // [B,H,S,HD] (Q pre-scaled 1/8)
__device__ __align__(256) __half g_kf[BB*HH*SS*HDIM];
__device__ __align__(256) __half g_vf[BB*HH*SS*HDIM];

__device__ __align__(256) __half g_xf[(size_t)M_TOT*DD];     // x fp16
__device__ __align__(256) __half g_wqkvf[(size_t)N_QKV*DD];  // W^T [N][K] fp16
__device__ __align__(256) __half g_woutf[(size_t)DD*DD];
__device__ __align__(256) __half g_aof[(size_t)M_TOT*DD];    // attn out fp16

// ---------------------------------------------------------------------------
// PTX helpers (base sm_80 ISA — harness lowers through compute_103)
// ---------------------------------------------------------------------------
__device__ __forceinline__ uint32_t smem_to_u32(const void* p) {
    uint32_t a;
    asm("{ .reg .u64 t; cvta.to.shared.u64 t, %1; cvt.u32.u64 %0, t; }"
        : "=r"(a) : "l"(p));
    return a;
}
#define CP_ASYNC16(sm, gp) \
    asm volatile("cp.async.cg.shared.global [%0], [%1], 16;" :: "r"(sm), "l"(gp) : "memory")
#define CP_COMMIT() asm volatile("cp.async.commit_group;" ::: "memory")
#define CP_WAIT2()  asm volatile("cp.async.wait_group 2;" ::: "memory")
#define CP_WAIT1()  asm volatile("cp.async.wait_group 1;" ::: "memory")
#define CP_WAIT0()  asm volatile("cp.async.wait_group 0;" ::: "memory")

#define SWZ128(o) ((o) ^ (((o) >> 3) & 0x70))

__device__ __forceinline__ void ldsm_x4(uint32_t& r0, uint32_t& r1,
                                        uint32_t& r2, uint32_t& r3, uint32_t a) {
    asm volatile("ldmatrix.sync.aligned.m8n8.x4.shared.b16 {%0,%1,%2,%3}, [%4];"
                 : "=r"(r0), "=r"(r1), "=r"(r2), "=r"(r3) : "r"(a));
}
__device__ __forceinline__ void ldsm_x4_t(uint32_t& r0, uint32_t& r1,
                                          uint32_t& r2, uint32_t& r3, uint32_t a) {
    asm volatile("ldmatrix.sync.aligned.m8n8.x4.trans.shared.b16 {%0,%1,%2,%3}, [%4];"
                 : "=r"(r0), "=r"(r1), "=r"(r2), "=r"(r3) : "r"(a));
}
__device__ __forceinline__ void mma16816h(float* c, const uint32_t* a,
                                          const uint32_t* b) {
    asm volatile(
        "mma.sync.aligned.m16n8k16.row.col.f32.f16.f16.f32 "
        "{%0,%1,%2,%3}, {%4,%5,%6,%7}, {%8,%9}, {%0,%1,%2,%3};"
        : "+f"(c[0]), "+f"(c[1]), "+f"(c[2]), "+f"(c[3])
        : "r"(a[0]), "r"(a[1]), "r"(a[2]), "r"(a[3]), "r"(b[0]), "r"(b[1]));
}
// pack two fp32 -> half2 (lo = v0, hi = v1)
__device__ __forceinline__ uint32_t pack_h2(float v0, float v1) {
    uint32_t r;
    asm("cvt.rn.f16x2.f32 %0, %1, %2;" : "=r"(r) : "f"(v1), "f"(v0));
    return r;
}

// ---------------------------------------------------------------------------
// prep kernels
// ---------------------------------------------------------------------------
// fp32 -> fp16 convert (vectorized)
__global__ __launch_bounds__(256) void conv_f16_kernel(
    const float4* __restrict__ in, uint2* __restrict__ out)
{
    int i = blockIdx.x * blockDim.x + threadIdx.x;
    float4 v = in[i];
    uint2 o;
    o.x = pack_h2(v.x, v.y);
    o.y = pack_h2(v.z, v.w);
    out[i] = o;
}

// W[K][N] fp32 -> W^T [N][K=1024] fp16
__global__ __launch_bounds__(256) void transpose_f16_kernel(
    const float* __restrict__ W, __half* __restrict__ T, int N)
{
    __shared__ float t[32][33];
    const int k0 = blockIdx.y * 32, n0 = blockIdx.x * 32;
    const int tx = threadIdx.x & 31, ty = threadIdx.x >> 5;
    #pragma unroll
    for (int j = 0; j < 4; j++)
        t[ty + j * 8][tx] = W[(size_t)(k0 + ty + j * 8) * N + n0 + tx];
    __syncthreads();
    #pragma unroll
    for (int j = 0; j < 4; j++) {
        const int n = n0 + ty + j * 8;
        T[(size_t)n * DD + k0 + tx] = __float2half(t[tx][ty + j * 8]);
    }
}

// ---------------------------------------------------------------------------
// mma.sync single-product fp16 GEMM: C = A[M,1024] @ W + bias.
// 512 threads (16 warps, 32x32 warp tiles), 128x128 CTA tile, K chunks of 64,
// 3-stage cp.async pipeline, 2 smem tiles/stage (A, B) = 96KB -> 2 CTAs/SM.
// QKV=true: result -> fp16, scattered to g_{q,k,v}f ([B,H,S,HD]); Q pre-scaled 1/8.
// ---------------------------------------------------------------------------
template<bool QKV>
__global__ __launch_bounds__(512)
void mma_gemm(const __half* __restrict__ A,
              const __half* __restrict__ B,
              const float* __restrict__ bias,
              float* __restrict__ C)
{
    extern __shared__ char smem[];
    const uint32_t sm0 = smem_to_u32(smem);   // stage s: +s*32768, tile t: +t*16384

    const int tid = threadIdx.x;
    const int wid = tid >> 5, lane = tid & 31;
    const int m0 = blockIdx.y * 128, n0 = blockIdx.x * 128;
    const int wm = wid & 3;     // 4 row groups of 32
    const int wn = wid >> 2;    // 4 col groups of 32

    const char* srcA = (const char*)(A + (size_t)m0 * DD);
    const char* srcB = (const char*)(B + (size_t)n0 * DD);

    auto load_stage = [&](int stage, int chunk) {
        const uint32_t sbase = sm0 + stage * 32768;
        const size_t coff = (size_t)chunk * 128;
        #pragma unroll
        for (int j = 0; j < 2; j++) {
            const int g = tid + j * 512;          // 1024 granules of 16B per tile
            const int r = g >> 3;
            const uint32_t cb = (uint32_t)((g & 7) * 16);
            const uint32_t so = SWZ128((uint32_t)(r * 128) + cb);
            CP_ASYNC16(sbase + so,         srcA + (size_t)r * (DD * 2) + coff + cb);
            CP_ASYNC16(sbase + 16384 + so, srcB + (size_t)r * (DD * 2) + coff + cb);
        }
        CP_COMMIT();
    };

    load_stage(0, 0);
    load_stage(1, 1);
    load_stage(2, 2);

    float acc[2][4][4] = {};

    const int sub   = lane >> 3;
    const int a_rin = (lane & 7) + (sub & 1) * 8;
    const int a_kh  = sub >> 1;
    const int b_nt  = sub >> 1;
    const int b_kh  = sub & 1;
    const int b_row = lane & 7;

    const int K_CHUNKS = DD / 64;  // 16
    for (int i = 0; i < K_CHUNKS; i++) {
        const int stage = i % 3;
        if (i <= K_CHUNKS - 3)      { CP_WAIT2(); }
        else if (i == K_CHUNKS - 2) { CP_WAIT1(); }
        else                        { CP_WAIT0(); }
        __syncthreads();

        const uint32_t Ab = sm0 + stage * 32768;
        const uint32_t Bb = Ab + 16384;

        #pragma unroll
        for (int ks = 0; ks < 4; ks++) {
            uint32_t af[2][4], bf[4][2];
            const uint32_t gka = (uint32_t)((ks * 2 + a_kh) * 16);
            #pragma unroll
            for (int mt = 0; mt < 2; mt++) {
                const uint32_t off =
                    SWZ128((uint32_t)((wm * 32 + mt * 16 + a_rin) * 128) + gka);
                ldsm_x4(af[mt][0], af[mt][1], af[mt][2], af[mt][3], Ab + off);
            }
            const uint32_t gkb = (uint32_t)((ks * 2 + b_kh) * 16);
            #pragma unroll
            for (int pr = 0; pr < 2; pr++) {
                const uint32_t off =
                    SWZ128((uint32_t)((wn * 32 + pr * 16 + b_nt * 8 + b_row) * 128) + gkb);
                uint32_t r0, r1, r2, r3;
                ldsm_x4(r0, r1, r2, r3, Bb + off);
                bf[pr * 2][0] = r0; bf[pr * 2][1] = r1;
                bf[pr * 2 + 1][0] = r2; bf[pr * 2 + 1][1] = r3;
            }
            #pragma unroll
            for (int mt = 0; mt < 2; mt++)
                #pragma unroll
                for (int nt = 0; nt < 4; nt++)
                    mma16816h(acc[mt][nt], af[mt], bf[nt]);
        }
        __syncthreads();
        if (i + 3 < K_CHUNKS) load_stage(stage, i + 3);
    }

    const int cg = lane >> 2, ctg = lane & 3;
    const int nb = n0 + wn * 32;

    if (QKV) {
        const int tsel = nb >> 10;
        const int h = (nb & 1023) >> 6;
        const int db = nb & 63;
        __half* dst = (tsel == 0) ? g_qf : (tsel == 1) ? g_kf : g_vf;
        const float sc = (tsel == 0) ? 0.125f : 1.0f;   // fold 1/sqrt(HD) into Q (exact)
        #pragma unroll
        for (int mt = 0; mt < 2; mt++) {
            const int ma = m0 + wm * 32 + mt * 16 + cg;
            const int mb = ma + 8;
            const int ba = ma >> 11, sa = ma & 2047;
            const int bb = mb >> 11, sbb = mb & 2047;
            const size_t ra = (((size_t)(ba * HH + h)) * SS + sa) * HDIM + db;
            const size_t rb = (((size_t)(bb * HH + h)) * SS + sbb) * HDIM + db;
            #pragma unroll
            for (int nt = 0; nt < 4; nt++) {
                const int cc = nt * 8 + ctg * 2;
                float2 bv = *(const float2*)(bias + nb + cc);
                *(uint32_t*)(dst + ra + cc) =
                    pack_h2((acc[mt][nt][0] + bv.x) * sc, (acc[mt][nt][1] + bv.y) * sc);
                *(uint32_t*)(dst + rb + cc) =
                    pack_h2((acc[mt][nt][2] + bv.x) * sc, (acc[mt][nt][3] + bv.y) * sc);
            }
        }
    } else {
        #pragma unroll
        for (int mt = 0; mt < 2; mt++) {
            const int ma = m0 + wm * 32 + mt * 16 + cg;
            float* pa = C + (size_t)ma * DD + nb;
            float* pb = C + (size_t)(ma + 8) * DD + nb;
            #pragma unroll
            for (int nt = 0; nt < 4; nt++) {
                const int cc = nt * 8 + ctg * 2;
                float2 bv = *(const float2*)(bias + nb + cc);
                *(float2*)(pa + cc) =
                    make_float2(acc[mt][nt][0] + bv.x, acc[mt][nt][1] + bv.y);
                *(float2*)(pb + cc) =
                    make_float2(acc[mt][nt][2] + bv.x, acc[mt][nt][3] + bv.y);
            }
        }
    }
}

// ---------------------------------------------------------------------------
// Flash attention, fp16 single-product mma.sync. 128-query CTA tile,
// 8 warps x 16 rows, key tiles of 64, 3-stage cp.async K/V pipeline.
// Q pre-scaled by 1/8 -> raw scores used directly.
// smem: Q 0..16K, P 16K..32K, stage st at 32K + st*16K (K 8K, V 8K). 80KB.
// ---------------------------------------------------------------------------
__global__ __launch_bounds__(256, 2)
void attn_mma_kernel()
{
    extern __shared__ char smem[];
    const uint32_t sm0 = smem_to_u32(smem);

    const int tid = threadIdx.x;
    const int w = tid >> 5, lane = tid & 31;
    const int bh = blockIdx.y;
    const int q0 = blockIdx.x * 128;

    const size_t bho = (size_t)bh * SS * HDIM;
    const char* qsrc = (const char*)(g_qf + bho + (size_t)q0 * HDIM);
    const char* ksrc = (const char*)(g_kf + bho);
    const char* vsrc = (const char*)(g_vf + bho);

    auto load_kv = [&](int stage, int kt) {
        const uint32_t sb = sm0 + 32768 + stage * 16384;
        const size_t roff = (size_t)(kt * 64) * 128;   // bytes
        #pragma unroll
        for (int j = 0; j < 2; j++) {
            const int g = tid + j * 256;               // 512 granules per tile
            const int r = g >> 3;
            const uint32_t cb = (uint32_t)((g & 7) * 16);
            const uint32_t so = SWZ128((uint32_t)(r * 128) + cb);
            CP_ASYNC16(sb + so,        ksrc + roff + (size_t)r * 128 + cb);
            CP_ASYNC16(sb + 8192 + so, vsrc + roff + (size_t)r * 128 + cb);
        }
    };

    // group 0: Q tile (128 rows x 128B) + KV stage 0
    #pragma unroll
    for (int j = 0; j < 4; j++) {
        const int g = tid + j * 256;                   // 1024 granules
        const int r = g >> 3;
        const uint32_t cb = (uint32_t)((g & 7) * 16);
        CP_ASYNC16(sm0 + SWZ128((uint32_t)(r * 128) + cb),
                   qsrc + (size_t)r * 128 + cb);
    }
    load_kv(0, 0);
    CP_COMMIT();
    load_kv(1, 1);
    CP_COMMIT();
    load_kv(2, 2);
    CP_COMMIT();

    const int sub   = lane >> 3;
    const int a_rin = (lane & 7) + (sub & 1) * 8;
    const int a_kh  = sub >> 1;
    const int b_nt  = sub >> 1;
    const int b_kh  = sub & 1;
    const int b_row = lane & 7;
    const int v_row = lane & 15;
    const int v_col = (lane >> 4) * 8;
    const int cg = lane >> 2, ctg = lane & 3;

    float acc_o[8][4] = {};
    float mi0 = -1e30f, mi1 = -1e30f, li0 = 0.f, li1 = 0.f;

    const int KT = SS / 64;  // 32
    for (int kt = 0; kt < KT; kt++) {
        const int stage = kt % 3;
        if (kt <= KT - 3)      { CP_WAIT2(); }
        else if (kt == KT - 2) { CP_WAIT1(); }
        else                   { CP_WAIT0(); }
        __syncthreads();

        const uint32_t Kb = sm0 + 32768 + stage * 16384;
        const uint32_t Vb = Kb + 8192;

        // ---- S = Q K^T (single fp16 product; Q pre-scaled) ----
        float acc_s[8][4] = {};
        #pragma unroll
        for (int ks = 0; ks < 4; ks++) {
            uint32_t ah[4];
            const uint32_t offa =
                SWZ128((uint32_t)((w * 16 + a_rin) * 128 + (ks * 2 + a_kh) * 16));
            ldsm_x4(ah[0], ah[1], ah[2], ah[3], sm0 + offa);
            #pragma unroll
            for (int pr = 0; pr < 4; pr++) {
                const uint32_t offb =
                    SWZ128((uint32_t)((pr * 16 + b_nt * 8 + b_row) * 128 + (ks * 2 + b_kh) * 16));
                uint32_t r0, r1, r2, r3;
                ldsm_x4(r0, r1, r2, r3, Kb + offb);
                uint32_t b0[2] = {r0, r1}, b1[2] = {r2, r3};
                mma16816h(acc_s[2 * pr],     ah, b0);
                mma16816h(acc_s[2 * pr + 1], ah, b1);
            }
        }

        // ---- online softmax (rows cg, cg+8; quad shfl reductions) ----
        float t0 = -1e30f, t1 = -1e30f;
        #pragma unroll
        for (int nt = 0; nt < 8; nt++) {
            t0 = fmaxf(t0, fmaxf(acc_s[nt][0], acc_s[nt][1]));
            t1 = fmaxf(t1, fmaxf(acc_s[nt][2], acc_s[nt][3]));
        }
        t0 = fmaxf(t0, __shfl_xor_sync(0xffffffffu, t0, 1));
        t0 = fmaxf(t0, __shfl_xor_sync(0xffffffffu, t0, 2));
        t1 = fmaxf(t1, __shfl_xor_sync(0xffffffffu, t1, 1));
        t1 = fmaxf(t1, __shfl_xor_sync(0xffffffffu, t1, 2));
        const float mn0 = fmaxf(mi0, t0);
        const float mn1 = fmaxf(mi1, t1);
        const float c0 = __expf(mi0 - mn0), c1 = __expf(mi1 - mn1);
        float rs0 = 0.f, rs1 = 0.f;
        #pragma unroll
        for (int nt = 0; nt < 8; nt++) {
            float p;
            p = __expf(acc_s[nt][0] - mn0); acc_s[nt][0] = p; rs0 += p;
            p = __expf(acc_s[nt][1] - mn0); acc_s[nt][1] = p; rs0 += p;
            p = __expf(acc_s[nt][2] - mn1); acc_s[nt][2] = p; rs1 += p;
            p = __expf(acc_s[nt][3] - mn1); acc_s[nt][3] = p; rs1 += p;
        }
        rs0 += __shfl_xor_sync(0xffffffffu, rs0, 1);
        rs0 += __shfl_xor_sync(0xffffffffu, rs0, 2);
        rs1 += __shfl_xor_sync(0xffffffffu, rs1, 1);
        rs1 += __shfl_xor_sync(0xffffffffu, rs1, 2);
        li0 = li0 * c0 + rs0;  li1 = li1 * c1 + rs1;
        mi0 = mn0;  mi1 = mn1;
        #pragma unroll
        for (int nt = 0; nt < 8; nt++) {
            acc_o[nt][0] *= c0; acc_o[nt][1] *= c0;
            acc_o[nt][2] *= c1; acc_o[nt][3] *= c1;
        }

        // ---- write P as fp16 to smem ----
        #pragma unroll
        for (int nt = 0; nt < 8; nt++) {
            const uint32_t off0 =
                SWZ128((uint32_t)((w * 16 + cg) * 128 + (nt * 8 + ctg * 2) * 2));
            *(uint32_t*)(smem + 16384 + off0) = pack_h2(acc_s[nt][0], acc_s[nt][1]);
            const uint32_t off1 =
                SWZ128((uint32_t)((w * 16 + cg + 8) * 128 + (nt * 8 + ctg * 2) * 2));
            *(uint32_t*)(smem + 16384 + off1) = pack_h2(acc_s[nt][2], acc_s[nt][3]);
        }
        __syncthreads();

        // ---- O += P V (fp16 single product; V via ldmatrix.trans) ----
        #pragma unroll
        for (int ks = 0; ks < 4; ks++) {
            uint32_t ah[4];
            const uint32_t offa =
                SWZ128((uint32_t)((w * 16 + a_rin) * 128 + (ks * 2 + a_kh) * 16));
            ldsm_x4(ah[0], ah[1], ah[2], ah[3], sm0 + 16384 + offa);
            #pragma unroll
            for (int pr = 0; pr < 4; pr++) {
                const uint32_t offv =
                    SWZ128((uint32_t)((ks * 16 + v_row) * 128 + (pr * 16 + v_col) * 2));
                uint32_t r0, r1, r2, r3;
                ldsm_x4_t(r0, r1, r2, r3, Vb + offv);
                uint32_t b0[2] = {r0, r1}, b1[2] = {r2, r3};
                mma16816h(acc_o[2 * pr],     ah, b0);
                mma16816h(acc_o[2 * pr + 1], ah, b1);
            }
        }
        __syncthreads();   // all warps done with this stage's K/V before refill

        if (kt + 3 < KT) {
            load_kv(stage, kt + 3);
            CP_COMMIT();
        }
    }

    // ---- epilogue: normalize, write single fp16 ao ----
    const int b = bh >> 4, hd = bh & 15;
    const float inv0 = 1.0f / li0, inv1 = 1.0f / li1;
    const int r0 = q0 + w * 16 + cg, r1 = r0 + 8;
    const size_t base0 = ((size_t)(b * SS + r0)) * DD + hd * HDIM;
    const size_t base1 = ((size_t)(b * SS + r1)) * DD + hd * HDIM;
    #pragma unroll
    for (int nt = 0; nt < 8; nt++) {
        const int cc = nt * 8 + ctg * 2;
        *(uint32_t*)(g_aof + base0 + cc) =
            pack_h2(acc_o[nt][0] * inv0, acc_o[nt][1] * inv0);
        *(uint32_t*)(g_aof + base1 + cc) =
            pack_h2(acc_o[nt][2] * inv1, acc_o[nt][3] * inv1);
    }
}

// ---------------------------------------------------------------------------
extern "C" void kernel_launch(void* const* d_in, const int* in_sizes, int n_in,
                              void* d_out, int out_size)
{
    const float* x     = (const float*)d_in[0];
    const float* W_qkv = (const float*)d_in[1];
    const float* b_qkv = (const float*)d_in[2];
    const float* W_out = (const float*)d_in[3];
    const float* b_out = (const float*)d_in[4];
    float* out = (float*)d_out;

    const int gemm_smem = 3 * 2 * 16384;           // 98304 (3 stages x 2 tiles)
    const int attn_smem = 2 * 16384 + 3 * 16384;   // 81920
    cudaFuncSetAttribute(mma_gemm<true>,
                         cudaFuncAttributeMaxDynamicSharedMemorySize, gemm_smem);
    cudaFuncSetAttribute(mma_gemm<false>,
                         cudaFuncAttributeMaxDynamicSharedMemorySize, gemm_smem);
    cudaFuncSetAttribute(attn_mma_kernel,
                         cudaFuncAttributeMaxDynamicSharedMemorySize, attn_smem);

    __half *xf, *wq, *wo, *aof;
    cudaGetSymbolAddress((void**)&xf,  g_xf);
    cudaGetSymbolAddress((void**)&wq,  g_wqkvf);
    cudaGetSymbolAddress((void**)&wo,  g_woutf);
    cudaGetSymbolAddress((void**)&aof, g_aof);

    // 0) prep: convert x to fp16, transpose weights to fp16 [N][K]
    conv_f16_kernel<<<(M_TOT * DD / 4) / 256, 256>>>(
        (const float4*)x, (uint2*)xf);
    transpose_f16_kernel<<<dim3(N_QKV / 32, DD / 32), 256>>>(W_qkv, wq, N_QKV);
    transpose_f16_kernel<<<dim3(DD / 32, DD / 32), 256>>>(W_out, wo, DD);

    // 1) QKV projection (single-product fp16) -> fp16 Q(pre-scaled),K,V
    mma_gemm<true><<<dim3(N_QKV / 128, M_TOT / 128), 512, gemm_smem>>>(
        xf, wq, b_qkv, nullptr);

    // 2) flash attention (fp16 mma.sync) -> fp16 ao
    attn_mma_kernel<<<dim3(SS / 128, BB * HH), 256, attn_smem>>>();

    // 3) output projection (single-product fp16, fp32 out)
    mma_gemm<false><<<dim3(DD / 128, M_TOT / 128), 512, gemm_smem>>>(
        aof, wo, b_out, out);
}

// round 16
// speedup vs baseline: 9.1752x; 1.1550x over previous
#include <cuda_runtime.h>
#include <cuda_fp16.h>
#include <cstdint>

#define DD 1024
#define HH 16
#define HDIM 64
#define BB 2
#define SS 2048
#define M_TOT (BB*SS)      // 4096
#define N_QKV (3*DD)       // 3072

// ---------------------------------------------------------------------------
// scratch (allocation-free rule: device globals)
// ---------------------------------------------------------------------------
__device__ __align__(256) __half g_qf[BB*HH*SS*HDIM];   // [B,H,S,HD] (Q pre-scaled 1/8)
__device__ __align__(256) __half g_kf[BB*HH*SS*HDIM];
__device__ __align__(256) __half g_vf[BB*HH*SS*HDIM];

__device__ __align__(256) __half g_xf[(size_t)M_TOT*DD];     // x fp16
__device__ __align__(256) __half g_wqkvf[(size_t)N_QKV*DD];  // W^T [N][K] fp16
__device__ __align__(256) __half g_woutf[(size_t)DD*DD];
__device__ __align__(256) __half g_aof[(size_t)M_TOT*DD];    // attn out fp16

// ---------------------------------------------------------------------------
// PTX helpers (base sm_80 ISA — harness lowers through compute_103)
// ---------------------------------------------------------------------------
__device__ __forceinline__ uint32_t smem_to_u32(const void* p) {
    uint32_t a;
    asm("{ .reg .u64 t; cvta.to.shared.u64 t, %1; cvt.u32.u64 %0, t; }"
        : "=r"(a) : "l"(p));
    return a;
}
#define CP_ASYNC16(sm, gp) \
    asm volatile("cp.async.cg.shared.global [%0], [%1], 16;" :: "r"(sm), "l"(gp) : "memory")
#define CP_COMMIT() asm volatile("cp.async.commit_group;" ::: "memory")
#define CP_WAIT2()  asm volatile("cp.async.wait_group 2;" ::: "memory")
#define CP_WAIT1()  asm volatile("cp.async.wait_group 1;" ::: "memory")
#define CP_WAIT0()  asm volatile("cp.async.wait_group 0;" ::: "memory")

#define SWZ128(o) ((o) ^ (((o) >> 3) & 0x70))

__device__ __forceinline__ void ldsm_x4(uint32_t& r0, uint32_t& r1,
                                        uint32_t& r2, uint32_t& r3, uint32_t a) {
    asm volatile("ldmatrix.sync.aligned.m8n8.x4.shared.b16 {%0,%1,%2,%3}, [%4];"
                 : "=r"(r0), "=r"(r1), "=r"(r2), "=r"(r3) : "r"(a));
}
__device__ __forceinline__ void ldsm_x4_t(uint32_t& r0, uint32_t& r1,
                                          uint32_t& r2, uint32_t& r3, uint32_t a) {
    asm volatile("ldmatrix.sync.aligned.m8n8.x4.trans.shared.b16 {%0,%1,%2,%3}, [%4];"
                 : "=r"(r0), "=r"(r1), "=r"(r2), "=r"(r3) : "r"(a));
}
__device__ __forceinline__ void mma16816h(float* c, const uint32_t* a,
                                          const uint32_t* b) {
    asm volatile(
        "mma.sync.aligned.m16n8k16.row.col.f32.f16.f16.f32 "
        "{%0,%1,%2,%3}, {%4,%5,%6,%7}, {%8,%9}, {%0,%1,%2,%3};"
        : "+f"(c[0]), "+f"(c[1]), "+f"(c[2]), "+f"(c[3])
        : "r"(a[0]), "r"(a[1]), "r"(a[2]), "r"(a[3]), "r"(b[0]), "r"(b[1]));
}
// pack two fp32 -> half2 (lo = v0, hi = v1)
__device__ __forceinline__ uint32_t pack_h2(float v0, float v1) {
    uint32_t r;
    asm("cvt.rn.f16x2.f32 %0, %1, %2;" : "=r"(r) : "f"(v1), "f"(v0));
    return r;
}

// ---------------------------------------------------------------------------
// prep kernels
// ---------------------------------------------------------------------------
__global__ __launch_bounds__(256) void conv_f16_kernel(
    const float4* __restrict__ in, uint2* __restrict__ out)
{
    int i = blockIdx.x * blockDim.x + threadIdx.x;
    float4 v = in[i];
    uint2 o;
    o.x = pack_h2(v.x, v.y);
    o.y = pack_h2(v.z, v.w);
    out[i] = o;
}

// W[K][N] fp32 -> W^T [N][K=1024] fp16
__global__ __launch_bounds__(256) void transpose_f16_kernel(
    const float* __restrict__ W, __half* __restrict__ T, int N)
{
    __shared__ float t[32][33];
    const int k0 = blockIdx.y * 32, n0 = blockIdx.x * 32;
    const int tx = threadIdx.x & 31, ty = threadIdx.x >> 5;
    #pragma unroll
    for (int j = 0; j < 4; j++)
        t[ty + j * 8][tx] = W[(size_t)(k0 + ty + j * 8) * N + n0 + tx];
    __syncthreads();
    #pragma unroll
    for (int j = 0; j < 4; j++) {
        const int n = n0 + ty + j * 8;
        T[(size_t)n * DD + k0 + tx] = __float2half(t[tx][ty + j * 8]);
    }
}

// ---------------------------------------------------------------------------
// mma.sync single-product fp16 GEMM: C = A[M,1024] @ W + bias.
// 256 threads, 8 warps at 64x32 warp tiles (2x4 grid), 128x128 CTA tile,
// K chunks of 64, 3-stage cp.async pipeline, 2 smem tiles/stage = 96KB.
// 2 CTAs/SM. QKV=true: fp16 scatter to g_{q,k,v}f; Q pre-scaled 1/8.
// ---------------------------------------------------------------------------
template<bool QKV>
__global__ __launch_bounds__(256, 2)
void mma_gemm(const __half* __restrict__ A,
              const __half* __restrict__ B,
              const float* __restrict__ bias,
              float* __restrict__ C)
{
    extern __shared__ char smem[];
    const uint32_t sm0 = smem_to_u32(smem);   // stage s: +s*32768 (A 16K, B 16K)

    const int tid = threadIdx.x;
    const int wid = tid >> 5, lane = tid & 31;
    const int m0 = blockIdx.y * 128, n0 = blockIdx.x * 128;
    const int wm = wid & 1;     // 2 row groups of 64
    const int wn = wid >> 1;    // 4 col groups of 32

    const char* srcA = (const char*)(A + (size_t)m0 * DD);
    const char* srcB = (const char*)(B + (size_t)n0 * DD);

    auto load_stage = [&](int stage, int chunk) {
        const uint32_t sbase = sm0 + stage * 32768;
        const size_t coff = (size_t)chunk * 128;
        #pragma unroll
        for (int j = 0; j < 4; j++) {
            const int g = tid + j * 256;          // 1024 granules of 16B per tile
            const int r = g >> 3;
            const uint32_t cb = (uint32_t)((g & 7) * 16);
            const uint32_t so = SWZ128((uint32_t)(r * 128) + cb);
            CP_ASYNC16(sbase + so,         srcA + (size_t)r * (DD * 2) + coff + cb);
            CP_ASYNC16(sbase + 16384 + so, srcB + (size_t)r * (DD * 2) + coff + cb);
        }
        CP_COMMIT();
    };

    load_stage(0, 0);
    load_stage(1, 1);
    load_stage(2, 2);

    float acc[4][4][4] = {};   // [mtile 16][ntile 8][c]

    const int sub   = lane >> 3;
    const int a_rin = (lane & 7) + (sub & 1) * 8;
    const int a_kh  = sub >> 1;
    const int b_nt  = sub >> 1;
    const int b_kh  = sub & 1;
    const int b_row = lane & 7;

    const int K_CHUNKS = DD / 64;  // 16
    for (int i = 0; i < K_CHUNKS; i++) {
        const int stage = i % 3;
        if (i <= K_CHUNKS - 3)      { CP_WAIT2(); }
        else if (i == K_CHUNKS - 2) { CP_WAIT1(); }
        else                        { CP_WAIT0(); }
        __syncthreads();

        const uint32_t Ab = sm0 + stage * 32768;
        const uint32_t Bb = Ab + 16384;

        #pragma unroll
        for (int ks = 0; ks < 4; ks++) {
            uint32_t af[4][4], bf[4][2];
            const uint32_t gka = (uint32_t)((ks * 2 + a_kh) * 16);
            #pragma unroll
            for (int mt = 0; mt < 4; mt++) {
                const uint32_t off =
                    SWZ128((uint32_t)((wm * 64 + mt * 16 + a_rin) * 128) + gka);
                ldsm_x4(af[mt][0], af[mt][1], af[mt][2], af[mt][3], Ab + off);
            }
            const uint32_t gkb = (uint32_t)((ks * 2 + b_kh) * 16);
            #pragma unroll
            for (int pr = 0; pr < 2; pr++) {
                const uint32_t off =
                    SWZ128((uint32_t)((wn * 32 + pr * 16 + b_nt * 8 + b_row) * 128) + gkb);
                uint32_t r0, r1, r2, r3;
                ldsm_x4(r0, r1, r2, r3, Bb + off);
                bf[pr * 2][0] = r0; bf[pr * 2][1] = r1;
                bf[pr * 2 + 1][0] = r2; bf[pr * 2 + 1][1] = r3;
            }
            #pragma unroll
            for (int mt = 0; mt < 4; mt++)
                #pragma unroll
                for (int nt = 0; nt < 4; nt++)
                    mma16816h(acc[mt][nt], af[mt], bf[nt]);
        }
        __syncthreads();
        if (i + 3 < K_CHUNKS) load_stage(stage, i + 3);
    }

    const int cg = lane >> 2, ctg = lane & 3;
    const int nb = n0 + wn * 32;

    if (QKV) {
        const int tsel = nb >> 10;
        const int h = (nb & 1023) >> 6;
        const int db = nb & 63;
        __half* dst = (tsel == 0) ? g_qf : (tsel == 1) ? g_kf : g_vf;
        const float sc = (tsel == 0) ? 0.125f : 1.0f;   // fold 1/sqrt(HD) into Q
        #pragma unroll
        for (int mt = 0; mt < 4; mt++) {
            const int ma = m0 + wm * 64 + mt * 16 + cg;
            const int mb = ma + 8;
            const int ba = ma >> 11, sa = ma & 2047;
            const int bb = mb >> 11, sbb = mb & 2047;
            const size_t ra = (((size_t)(ba * HH + h)) * SS + sa) * HDIM + db;
            const size_t rb = (((size_t)(bb * HH + h)) * SS + sbb) * HDIM + db;
            #pragma unroll
            for (int nt = 0; nt < 4; nt++) {
                const int cc = nt * 8 + ctg * 2;
                float2 bv = *(const float2*)(bias + nb + cc);
                *(uint32_t*)(dst + ra + cc) =
                    pack_h2((acc[mt][nt][0] + bv.x) * sc, (acc[mt][nt][1] + bv.y) * sc);
                *(uint32_t*)(dst + rb + cc) =
                    pack_h2((acc[mt][nt][2] + bv.x) * sc, (acc[mt][nt][3] + bv.y) * sc);
            }
        }
    } else {
        #pragma unroll
        for (int mt = 0; mt < 4; mt++) {
            const int ma = m0 + wm * 64 + mt * 16 + cg;
            float* pa = C + (size_t)ma * DD + nb;
            float* pb = C + (size_t)(ma + 8) * DD + nb;
            #pragma unroll
            for (int nt = 0; nt < 4; nt++) {
                const int cc = nt * 8 + ctg * 2;
                float2 bv = *(const float2*)(bias + nb + cc);
                *(float2*)(pa + cc) =
                    make_float2(acc[mt][nt][0] + bv.x, acc[mt][nt][1] + bv.y);
                *(float2*)(pb + cc) =
                    make_float2(acc[mt][nt][2] + bv.x, acc[mt][nt][3] + bv.y);
            }
        }
    }
}

// ---------------------------------------------------------------------------
// Flash attention, fp16 mma.sync with REGISTER-RESIDENT P:
// the m16n8 C-fragment of S is bit-identical in layout to the m16k16
// A-fragment needed by PV after pack_h2 — P never touches smem.
// 128-query CTA tile, 8 warps x 16 rows, key tiles of 64,
// 3-stage cp.async K/V pipeline. Q pre-scaled 1/8.
// smem: Q 0..16K, stage st at 16K + st*16K (K 8K, V 8K). 64KB total.
// ---------------------------------------------------------------------------
__global__ __launch_bounds__(256, 2)
void attn_mma_kernel()
{
    extern __shared__ char smem[];
    const uint32_t sm0 = smem_to_u32(smem);

    const int tid = threadIdx.x;
    const int w = tid >> 5, lane = tid & 31;
    const int bh = blockIdx.y;
    const int q0 = blockIdx.x * 128;

    const size_t bho = (size_t)bh * SS * HDIM;
    const char* qsrc = (const char*)(g_qf + bho + (size_t)q0 * HDIM);
    const char* ksrc = (const char*)(g_kf + bho);
    const char* vsrc = (const char*)(g_vf + bho);

    auto load_kv = [&](int stage, int kt) {
        const uint32_t sb = sm0 + 16384 + stage * 16384;
        const size_t roff = (size_t)(kt * 64) * 128;   // bytes
        #pragma unroll
        for (int j = 0; j < 2; j++) {
            const int g = tid + j * 256;               // 512 granules per tile
            const int r = g >> 3;
            const uint32_t cb = (uint32_t)((g & 7) * 16);
            const uint32_t so = SWZ128((uint32_t)(r * 128) + cb);
            CP_ASYNC16(sb + so,        ksrc + roff + (size_t)r * 128 + cb);
            CP_ASYNC16(sb + 8192 + so, vsrc + roff + (size_t)r * 128 + cb);
        }
    };

    // group 0: Q tile (128 rows x 128B) + KV stage 0
    #pragma unroll
    for (int j = 0; j < 4; j++) {
        const int g = tid + j * 256;                   // 1024 granules
        const int r = g >> 3;
        const uint32_t cb = (uint32_t)((g & 7) * 16);
        CP_ASYNC16(sm0 + SWZ128((uint32_t)(r * 128) + cb),
                   qsrc + (size_t)r * 128 + cb);
    }
    load_kv(0, 0);
    CP_COMMIT();
    load_kv(1, 1);
    CP_COMMIT();
    load_kv(2, 2);
    CP_COMMIT();

    const int sub   = lane >> 3;
    const int a_rin = (lane & 7) + (sub & 1) * 8;
    const int a_kh  = sub >> 1;
    const int b_nt  = sub >> 1;
    const int b_kh  = sub & 1;
    const int b_row = lane & 7;
    const int v_row = lane & 15;
    const int v_col = (lane >> 4) * 8;
    const int cg = lane >> 2, ctg = lane & 3;

    float acc_o[8][4] = {};
    float mi0 = -1e30f, mi1 = -1e30f, li0 = 0.f, li1 = 0.f;

    const int KT = SS / 64;  // 32
    for (int kt = 0; kt < KT; kt++) {
        const int stage = kt % 3;
        if (kt <= KT - 3)      { CP_WAIT2(); }
        else if (kt == KT - 2) { CP_WAIT1(); }
        else                   { CP_WAIT0(); }
        __syncthreads();

        const uint32_t Kb = sm0 + 16384 + stage * 16384;
        const uint32_t Vb = Kb + 8192;

        // ---- S = Q K^T (single fp16 product; Q pre-scaled) ----
        float acc_s[8][4] = {};
        #pragma unroll
        for (int ks = 0; ks < 4; ks++) {
            uint32_t ah[4];
            const uint32_t offa =
                SWZ128((uint32_t)((w * 16 + a_rin) * 128 + (ks * 2 + a_kh) * 16));
            ldsm_x4(ah[0], ah[1], ah[2], ah[3], sm0 + offa);
            #pragma unroll
            for (int pr = 0; pr < 4; pr++) {
                const uint32_t offb =
                    SWZ128((uint32_t)((pr * 16 + b_nt * 8 + b_row) * 128 + (ks * 2 + b_kh) * 16));
                uint32_t r0, r1, r2, r3;
                ldsm_x4(r0, r1, r2, r3, Kb + offb);
                uint32_t b0[2] = {r0, r1}, b1[2] = {r2, r3};
                mma16816h(acc_s[2 * pr],     ah, b0);
                mma16816h(acc_s[2 * pr + 1], ah, b1);
            }
        }

        // ---- online softmax (rows cg, cg+8; quad shfl reductions) ----
        float t0 = -1e30f, t1 = -1e30f;
        #pragma unroll
        for (int nt = 0; nt < 8; nt++) {
            t0 = fmaxf(t0, fmaxf(acc_s[nt][0], acc_s[nt][1]));
            t1 = fmaxf(t1, fmaxf(acc_s[nt][2], acc_s[nt][3]));
        }
        t0 = fmaxf(t0, __shfl_xor_sync(0xffffffffu, t0, 1));
        t0 = fmaxf(t0, __shfl_xor_sync(0xffffffffu, t0, 2));
        t1 = fmaxf(t1, __shfl_xor_sync(0xffffffffu, t1, 1));
        t1 = fmaxf(t1, __shfl_xor_sync(0xffffffffu, t1, 2));
        const float mn0 = fmaxf(mi0, t0);
        const float mn1 = fmaxf(mi1, t1);
        const float c0 = __expf(mi0 - mn0), c1 = __expf(mi1 - mn1);
        float rs0 = 0.f, rs1 = 0.f;
        #pragma unroll
        for (int nt = 0; nt < 8; nt++) {
            float p;
            p = __expf(acc_s[nt][0] - mn0); acc_s[nt][0] = p; rs0 += p;
            p = __expf(acc_s[nt][1] - mn0); acc_s[nt][1] = p; rs0 += p;
            p = __expf(acc_s[nt][2] - mn1); acc_s[nt][2] = p; rs1 += p;
            p = __expf(acc_s[nt][3] - mn1); acc_s[nt][3] = p; rs1 += p;
        }
        rs0 += __shfl_xor_sync(0xffffffffu, rs0, 1);
        rs0 += __shfl_xor_sync(0xffffffffu, rs0, 2);
        rs1 += __shfl_xor_sync(0xffffffffu, rs1, 1);
        rs1 += __shfl_xor_sync(0xffffffffu, rs1, 2);
        li0 = li0 * c0 + rs0;  li1 = li1 * c1 + rs1;
        mi0 = mn0;  mi1 = mn1;
        #pragma unroll
        for (int nt = 0; nt < 8; nt++) {
            acc_o[nt][0] *= c0; acc_o[nt][1] *= c0;
            acc_o[nt][2] *= c1; acc_o[nt][3] *= c1;
        }

        // ---- pack P into A-fragments in registers (C-layout == A-layout) ----
        // A frag for k16-step ks: a0=(row cg, k=2ctg),   a1=(row cg+8, k=2ctg),
        //                         a2=(row cg, k=8+2ctg), a3=(row cg+8, k=8+2ctg)
        // n-tile 2ks covers keys [16ks, 16ks+8) and 2ks+1 covers [16ks+8, 16ks+16).
        uint32_t ap[4][4];
        #pragma unroll
        for (int ks = 0; ks < 4; ks++) {
            ap[ks][0] = pack_h2(acc_s[2 * ks][0],     acc_s[2 * ks][1]);
            ap[ks][1] = pack_h2(acc_s[2 * ks][2],     acc_s[2 * ks][3]);
            ap[ks][2] = pack_h2(acc_s[2 * ks + 1][0], acc_s[2 * ks + 1][1]);
            ap[ks][3] = pack_h2(acc_s[2 * ks + 1][2], acc_s[2 * ks + 1][3]);
        }

        // ---- O += P V (P from registers; V via ldmatrix.trans) ----
        #pragma unroll
        for (int ks = 0; ks < 4; ks++) {
            #pragma unroll
            for (int pr = 0; pr < 4; pr++) {
                const uint32_t offv =
                    SWZ128((uint32_t)((ks * 16 + v_row) * 128 + (pr * 16 + v_col) * 2));
                uint32_t r0, r1, r2, r3;
                ldsm_x4_t(r0, r1, r2, r3, Vb + offv);
                uint32_t b0[2] = {r0, r1}, b1[2] = {r2, r3};
                mma16816h(acc_o[2 * pr],     ap[ks], b0);
                mma16816h(acc_o[2 * pr + 1], ap[ks], b1);
            }
        }
        __syncthreads();   // all warps done with this stage's K/V before refill

        if (kt + 3 < KT) {
            load_kv(stage, kt + 3);
            CP_COMMIT();
        }
    }

    // ---- epilogue: normalize, write single fp16 ao ----
    const int b = bh >> 4, hd = bh & 15;
    const float inv0 = 1.0f / li0, inv1 = 1.0f / li1;
    const int r0 = q0 + w * 16 + cg, r1 = r0 + 8;
    const size_t base0 = ((size_t)(b * SS + r0)) * DD + hd * HDIM;
    const size_t base1 = ((size_t)(b * SS + r1)) * DD + hd * HDIM;
    #pragma unroll
    for (int nt = 0; nt < 8; nt++) {
        const int cc = nt * 8 + ctg * 2;
        *(uint32_t*)(g_aof + base0 + cc) =
            pack_h2(acc_o[nt][0] * inv0, acc_o[nt][1] * inv0);
        *(uint32_t*)(g_aof + base1 + cc) =
            pack_h2(acc_o[nt][2] * inv1, acc_o[nt][3] * inv1);
    }
}

// ---------------------------------------------------------------------------
extern "C" void kernel_launch(void* const* d_in, const int* in_sizes, int n_in,
                              void* d_out, int out_size)
{
    const float* x     = (const float*)d_in[0];
    const float* W_qkv = (const float*)d_in[1];
    const float* b_qkv = (const float*)d_in[2];
    const float* W_out = (const float*)d_in[3];
    const float* b_out = (const float*)d_in[4];
    float* out = (float*)d_out;

    const int gemm_smem = 3 * 2 * 16384;           // 98304 (3 stages x 2 tiles)
    const int attn_smem = 16384 + 3 * 16384;       // 65536 (Q + 3 KV stages)
    cudaFuncSetAttribute(mma_gemm<true>,
                         cudaFuncAttributeMaxDynamicSharedMemorySize, gemm_smem);
    cudaFuncSetAttribute(mma_gemm<false>,
                         cudaFuncAttributeMaxDynamicSharedMemorySize, gemm_smem);
    cudaFuncSetAttribute(attn_mma_kernel,
                         cudaFuncAttributeMaxDynamicSharedMemorySize, attn_smem);

    __half *xf, *wq, *wo, *aof;
    cudaGetSymbolAddress((void**)&xf,  g_xf);
    cudaGetSymbolAddress((void**)&wq,  g_wqkvf);
    cudaGetSymbolAddress((void**)&wo,  g_woutf);
    cudaGetSymbolAddress((void**)&aof, g_aof);

    // 0) prep: convert x to fp16, transpose weights to fp16 [N][K]
    conv_f16_kernel<<<(M_TOT * DD / 4) / 256, 256>>>(
        (const float4*)x, (uint2*)xf);
    transpose_f16_kernel<<<dim3(N_QKV / 32, DD / 32), 256>>>(W_qkv, wq, N_QKV);
    transpose_f16_kernel<<<dim3(DD / 32, DD / 32), 256>>>(W_out, wo, DD);

    // 1) QKV projection (single-product fp16) -> fp16 Q(pre-scaled),K,V
    mma_gemm<true><<<dim3(N_QKV / 128, M_TOT / 128), 256, gemm_smem>>>(
        xf, wq, b_qkv, nullptr);

    // 2) flash attention (fp16 mma.sync, register-resident P) -> fp16 ao
    attn_mma_kernel<<<dim3(SS / 128, BB * HH), 256, attn_smem>>>();

    // 3) output projection (single-product fp16, fp32 out)
    mma_gemm<false><<<dim3(DD / 128, M_TOT / 128), 256, gemm_smem>>>(
        aof, wo, b_out, out);
}

// round 17
// speedup vs baseline: 9.1863x; 1.0012x over previous
#include <cuda_runtime.h>
#include <cuda_fp16.h>
#include <cstdint>

#define DD 1024
#define HH 16
#define HDIM 64
#define BB 2
#define SS 2048
#define M_TOT (BB*SS)      // 4096
#define N_QKV (3*DD)       // 3072

// ---------------------------------------------------------------------------
// scratch (allocation-free rule: device globals)
// ---------------------------------------------------------------------------
__device__ __align__(256) __half g_qf[BB*HH*SS*HDIM];   // [B,H,S,HD] (Q pre-scaled 1/8)
__device__ __align__(256) __half g_kf[BB*HH*SS*HDIM];
__device__ __align__(256) __half g_vf[BB*HH*SS*HDIM];

__device__ __align__(256) __half g_xf[(size_t)M_TOT*DD];     // x fp16
__device__ __align__(256) __half g_wqkvf[(size_t)N_QKV*DD];  // W^T [N][K] fp16
__device__ __align__(256) __half g_woutf[(size_t)DD*DD];
__device__ __align__(256) __half g_aof[(size_t)M_TOT*DD];    // attn out fp16

// ---------------------------------------------------------------------------
// PTX helpers (base sm_80 ISA — harness lowers through compute_103)
// ---------------------------------------------------------------------------
__device__ __forceinline__ uint32_t smem_to_u32(const void* p) {
    uint32_t a;
    asm("{ .reg .u64 t; cvta.to.shared.u64 t, %1; cvt.u32.u64 %0, t; }"
        : "=r"(a) : "l"(p));
    return a;
}
#define CP_ASYNC16(sm, gp) \
    asm volatile("cp.async.cg.shared.global [%0], [%1], 16;" :: "r"(sm), "l"(gp) : "memory")
#define CP_COMMIT() asm volatile("cp.async.commit_group;" ::: "memory")
#define CP_WAIT2()  asm volatile("cp.async.wait_group 2;" ::: "memory")
#define CP_WAIT1()  asm volatile("cp.async.wait_group 1;" ::: "memory")
#define CP_WAIT0()  asm volatile("cp.async.wait_group 0;" ::: "memory")

#define SWZ128(o) ((o) ^ (((o) >> 3) & 0x70))

__device__ __forceinline__ void ldsm_x4(uint32_t& r0, uint32_t& r1,
                                        uint32_t& r2, uint32_t& r3, uint32_t a) {
    asm volatile("ldmatrix.sync.aligned.m8n8.x4.shared.b16 {%0,%1,%2,%3}, [%4];"
                 : "=r"(r0), "=r"(r1), "=r"(r2), "=r"(r3) : "r"(a));
}
__device__ __forceinline__ void ldsm_x4_t(uint32_t& r0, uint32_t& r1,
                                          uint32_t& r2, uint32_t& r3, uint32_t a) {
    asm volatile("ldmatrix.sync.aligned.m8n8.x4.trans.shared.b16 {%0,%1,%2,%3}, [%4];"
                 : "=r"(r0), "=r"(r1), "=r"(r2), "=r"(r3) : "r"(a));
}
__device__ __forceinline__ void mma16816h(float* c, const uint32_t* a,
                                          const uint32_t* b) {
    asm volatile(
        "mma.sync.aligned.m16n8k16.row.col.f32.f16.f16.f32 "
        "{%0,%1,%2,%3}, {%4,%5,%6,%7}, {%8,%9}, {%0,%1,%2,%3};"
        : "+f"(c[0]), "+f"(c[1]), "+f"(c[2]), "+f"(c[3])
        : "r"(a[0]), "r"(a[1]), "r"(a[2]), "r"(a[3]), "r"(b[0]), "r"(b[1]));
}
// pack two fp32 -> half2 (lo = v0, hi = v1)
__device__ __forceinline__ uint32_t pack_h2(float v0, float v1) {
    uint32_t r;
    asm("cvt.rn.f16x2.f32 %0, %1, %2;" : "=r"(r) : "f"(v1), "f"(v0));
    return r;
}

// ---------------------------------------------------------------------------
// prep kernels
// ---------------------------------------------------------------------------
__global__ __launch_bounds__(256) void conv_f16_kernel(
    const float4* __restrict__ in, uint2* __restrict__ out)
{
    int i = blockIdx.x * blockDim.x + threadIdx.x;
    float4 v = in[i];
    uint2 o;
    o.x = pack_h2(v.x, v.y);
    o.y = pack_h2(v.z, v.w);
    out[i] = o;
}

// W[K][N] fp32 -> W^T [N][K=1024] fp16
__global__ __launch_bounds__(256) void transpose_f16_kernel(
    const float* __restrict__ W, __half* __restrict__ T, int N)
{
    __shared__ float t[32][33];
    const int k0 = blockIdx.y * 32, n0 = blockIdx.x * 32;
    const int tx = threadIdx.x & 31, ty = threadIdx.x >> 5;
    #pragma unroll
    for (int j = 0; j < 4; j++)
        t[ty + j * 8][tx] = W[(size_t)(k0 + ty + j * 8) * N + n0 + tx];
    __syncthreads();
    #pragma unroll
    for (int j = 0; j < 4; j++) {
        const int n = n0 + ty + j * 8;
        T[(size_t)n * DD + k0 + tx] = __float2half(t[tx][ty + j * 8]);
    }
}

// ---------------------------------------------------------------------------
// mma.sync single-product fp16 GEMM: C = A[M,1024] @ W + bias.
// 256 threads, 8 warps at 64x32 warp tiles (2x4 grid), 128x128 CTA tile,
// K chunks of 64, 3-stage cp.async pipeline, 2 smem tiles/stage = 96KB.
// 2 CTAs/SM. QKV=true: fp16 scatter to g_{q,k,v}f; Q pre-scaled 1/8.
// ---------------------------------------------------------------------------
template<bool QKV>
__global__ __launch_bounds__(256, 2)
void mma_gemm(const __half* __restrict__ A,
              const __half* __restrict__ B,
              const float* __restrict__ bias,
              float* __restrict__ C)
{
    extern __shared__ char smem[];
    const uint32_t sm0 = smem_to_u32(smem);   // stage s: +s*32768 (A 16K, B 16K)

    const int tid = threadIdx.x;
    const int wid = tid >> 5, lane = tid & 31;
    const int m0 = blockIdx.y * 128, n0 = blockIdx.x * 128;
    const int wm = wid & 1;     // 2 row groups of 64
    const int wn = wid >> 1;    // 4 col groups of 32

    const char* srcA = (const char*)(A + (size_t)m0 * DD);
    const char* srcB = (const char*)(B + (size_t)n0 * DD);

    auto load_stage = [&](int stage, int chunk) {
        const uint32_t sbase = sm0 + stage * 32768;
        const size_t coff = (size_t)chunk * 128;
        #pragma unroll
        for (int j = 0; j < 4; j++) {
            const int g = tid + j * 256;          // 1024 granules of 16B per tile
            const int r = g >> 3;
            const uint32_t cb = (uint32_t)((g & 7) * 16);
            const uint32_t so = SWZ128((uint32_t)(r * 128) + cb);
            CP_ASYNC16(sbase + so,         srcA + (size_t)r * (DD * 2) + coff + cb);
            CP_ASYNC16(sbase + 16384 + so, srcB + (size_t)r * (DD * 2) + coff + cb);
        }
        CP_COMMIT();
    };

    load_stage(0, 0);
    load_stage(1, 1);
    load_stage(2, 2);

    float acc[4][4][4] = {};   // [mtile 16][ntile 8][c]

    const int sub   = lane >> 3;
    const int a_rin = (lane & 7) + (sub & 1) * 8;
    const int a_kh  = sub >> 1;
    const int b_nt  = sub >> 1;
    const int b_kh  = sub & 1;
    const int b_row = lane & 7;

    const int K_CHUNKS = DD / 64;  // 16
    for (int i = 0; i < K_CHUNKS; i++) {
        const int stage = i % 3;
        if (i <= K_CHUNKS - 3)      { CP_WAIT2(); }
        else if (i == K_CHUNKS - 2) { CP_WAIT1(); }
        else                        { CP_WAIT0(); }
        __syncthreads();

        const uint32_t Ab = sm0 + stage * 32768;
        const uint32_t Bb = Ab + 16384;

        #pragma unroll
        for (int ks = 0; ks < 4; ks++) {
            uint32_t af[4][4], bf[4][2];
            const uint32_t gka = (uint32_t)((ks * 2 + a_kh) * 16);
            #pragma unroll
            for (int mt = 0; mt < 4; mt++) {
                const uint32_t off =
                    SWZ128((uint32_t)((wm * 64 + mt * 16 + a_rin) * 128) + gka);
                ldsm_x4(af[mt][0], af[mt][1], af[mt][2], af[mt][3], Ab + off);
            }
            const uint32_t gkb = (uint32_t)((ks * 2 + b_kh) * 16);
            #pragma unroll
            for (int pr = 0; pr < 2; pr++) {
                const uint32_t off =
                    SWZ128((uint32_t)((wn * 32 + pr * 16 + b_nt * 8 + b_row) * 128) + gkb);
                uint32_t r0, r1, r2, r3;
                ldsm_x4(r0, r1, r2, r3, Bb + off);
                bf[pr * 2][0] = r0; bf[pr * 2][1] = r1;
                bf[pr * 2 + 1][0] = r2; bf[pr * 2 + 1][1] = r3;
            }
            #pragma unroll
            for (int mt = 0; mt < 4; mt++)
                #pragma unroll
                for (int nt = 0; nt < 4; nt++)
                    mma16816h(acc[mt][nt], af[mt], bf[nt]);
        }
        __syncthreads();
        if (i + 3 < K_CHUNKS) load_stage(stage, i + 3);
    }

    const int cg = lane >> 2, ctg = lane & 3;
    const int nb = n0 + wn * 32;

    if (QKV) {
        const int tsel = nb >> 10;
        const int h = (nb & 1023) >> 6;
        const int db = nb & 63;
        __half* dst = (tsel == 0) ? g_qf : (tsel == 1) ? g_kf : g_vf;
        const float sc = (tsel == 0) ? 0.125f : 1.0f;   // fold 1/sqrt(HD) into Q
        #pragma unroll
        for (int mt = 0; mt < 4; mt++) {
            const int ma = m0 + wm * 64 + mt * 16 + cg;
            const int mb = ma + 8;
            const int ba = ma >> 11, sa = ma & 2047;
            const int bb = mb >> 11, sbb = mb & 2047;
            const size_t ra = (((size_t)(ba * HH + h)) * SS + sa) * HDIM + db;
            const size_t rb = (((size_t)(bb * HH + h)) * SS + sbb) * HDIM + db;
            #pragma unroll
            for (int nt = 0; nt < 4; nt++) {
                const int cc = nt * 8 + ctg * 2;
                float2 bv = *(const float2*)(bias + nb + cc);
                *(uint32_t*)(dst + ra + cc) =
                    pack_h2((acc[mt][nt][0] + bv.x) * sc, (acc[mt][nt][1] + bv.y) * sc);
                *(uint32_t*)(dst + rb + cc) =
                    pack_h2((acc[mt][nt][2] + bv.x) * sc, (acc[mt][nt][3] + bv.y) * sc);
            }
        }
    } else {
        #pragma unroll
        for (int mt = 0; mt < 4; mt++) {
            const int ma = m0 + wm * 64 + mt * 16 + cg;
            float* pa = C + (size_t)ma * DD + nb;
            float* pb = C + (size_t)(ma + 8) * DD + nb;
            #pragma unroll
            for (int nt = 0; nt < 4; nt++) {
                const int cc = nt * 8 + ctg * 2;
                float2 bv = *(const float2*)(bias + nb + cc);
                *(float2*)(pa + cc) =
                    make_float2(acc[mt][nt][0] + bv.x, acc[mt][nt][1] + bv.y);
                *(float2*)(pb + cc) =
                    make_float2(acc[mt][nt][2] + bv.x, acc[mt][nt][3] + bv.y);
            }
        }
    }
}

// ---------------------------------------------------------------------------
// Flash attention, fp16 mma.sync with REGISTER-RESIDENT P:
// the m16n8 C-fragment of S is bit-identical in layout to the m16k16
// A-fragment needed by PV after pack_h2 — P never touches smem.
// 128-query CTA tile, 8 warps x 16 rows, key tiles of 64,
// 3-stage cp.async K/V pipeline. Q pre-scaled 1/8.
// smem: Q 0..16K, stage st at 16K + st*16K (K 8K, V 8K). 64KB total.
// ---------------------------------------------------------------------------
__global__ __launch_bounds__(256, 2)
void attn_mma_kernel()
{
    extern __shared__ char smem[];
    const uint32_t sm0 = smem_to_u32(smem);

    const int tid = threadIdx.x;
    const int w = tid >> 5, lane = tid & 31;
    const int bh = blockIdx.y;
    const int q0 = blockIdx.x * 128;

    const size_t bho = (size_t)bh * SS * HDIM;
    const char* qsrc = (const char*)(g_qf + bho + (size_t)q0 * HDIM);
    const char* ksrc = (const char*)(g_kf + bho);
    const char* vsrc = (const char*)(g_vf + bho);

    auto load_kv = [&](int stage, int kt) {
        const uint32_t sb = sm0 + 16384 + stage * 16384;
        const size_t roff = (size_t)(kt * 64) * 128;   // bytes
        #pragma unroll
        for (int j = 0; j < 2; j++) {
            const int g = tid + j * 256;               // 512 granules per tile
            const int r = g >> 3;
            const uint32_t cb = (uint32_t)((g & 7) * 16);
            const uint32_t so = SWZ128((uint32_t)(r * 128) + cb);
            CP_ASYNC16(sb + so,        ksrc + roff + (size_t)r * 128 + cb);
            CP_ASYNC16(sb + 8192 + so, vsrc + roff + (size_t)r * 128 + cb);
        }
    };

    // group 0: Q tile (128 rows x 128B) + KV stage 0
    #pragma unroll
    for (int j = 0; j < 4; j++) {
        const int g = tid + j * 256;                   // 1024 granules
        const int r = g >> 3;
        const uint32_t cb = (uint32_t)((g & 7) * 16);
        CP_ASYNC16(sm0 + SWZ128((uint32_t)(r * 128) + cb),
                   qsrc + (size_t)r * 128 + cb);
    }
    load_kv(0, 0);
    CP_COMMIT();
    load_kv(1, 1);
    CP_COMMIT();
    load_kv(2, 2);
    CP_COMMIT();

    const int sub   = lane >> 3;
    const int a_rin = (lane & 7) + (sub & 1) * 8;
    const int a_kh  = sub >> 1;
    const int b_nt  = sub >> 1;
    const int b_kh  = sub & 1;
    const int b_row = lane & 7;
    const int v_row = lane & 15;
    const int v_col = (lane >> 4) * 8;
    const int cg = lane >> 2, ctg = lane & 3;

    float acc_o[8][4] = {};
    float mi0 = -1e30f, mi1 = -1e30f, li0 = 0.f, li1 = 0.f;

    const int KT = SS / 64;  // 32
    for (int kt = 0; kt < KT; kt++) {
        const int stage = kt % 3;
        if (kt <= KT - 3)      { CP_WAIT2(); }
        else if (kt == KT - 2) { CP_WAIT1(); }
        else                   { CP_WAIT0(); }
        __syncthreads();

        const uint32_t Kb = sm0 + 16384 + stage * 16384;
        const uint32_t Vb = Kb + 8192;

        // ---- S = Q K^T (single fp16 product; Q pre-scaled) ----
        float acc_s[8][4] = {};
        #pragma unroll
        for (int ks = 0; ks < 4; ks++) {
            uint32_t ah[4];
            const uint32_t offa =
                SWZ128((uint32_t)((w * 16 + a_rin) * 128 + (ks * 2 + a_kh) * 16));
            ldsm_x4(ah[0], ah[1], ah[2], ah[3], sm0 + offa);
            #pragma unroll
            for (int pr = 0; pr < 4; pr++) {
                const uint32_t offb =
                    SWZ128((uint32_t)((pr * 16 + b_nt * 8 + b_row) * 128 + (ks * 2 + b_kh) * 16));
                uint32_t r0, r1, r2, r3;
                ldsm_x4(r0, r1, r2, r3, Kb + offb);
                uint32_t b0[2] = {r0, r1}, b1[2] = {r2, r3};
                mma16816h(acc_s[2 * pr],     ah, b0);
                mma16816h(acc_s[2 * pr + 1], ah, b1);
            }
        }

        // ---- online softmax (rows cg, cg+8; quad shfl reductions) ----
        float t0 = -1e30f, t1 = -1e30f;
        #pragma unroll
        for (int nt = 0; nt < 8; nt++) {
            t0 = fmaxf(t0, fmaxf(acc_s[nt][0], acc_s[nt][1]));
            t1 = fmaxf(t1, fmaxf(acc_s[nt][2], acc_s[nt][3]));
        }
        t0 = fmaxf(t0, __shfl_xor_sync(0xffffffffu, t0, 1));
        t0 = fmaxf(t0, __shfl_xor_sync(0xffffffffu, t0, 2));
        t1 = fmaxf(t1, __shfl_xor_sync(0xffffffffu, t1, 1));
        t1 = fmaxf(t1, __shfl_xor_sync(0xffffffffu, t1, 2));
        const float mn0 = fmaxf(mi0, t0);
        const float mn1 = fmaxf(mi1, t1);
        const float c0 = __expf(mi0 - mn0), c1 = __expf(mi1 - mn1);
        float rs0 = 0.f, rs1 = 0.f;
        #pragma unroll
        for (int nt = 0; nt < 8; nt++) {
            float p;
            p = __expf(acc_s[nt][0] - mn0); acc_s[nt][0] = p; rs0 += p;
            p = __expf(acc_s[nt][1] - mn0); acc_s[nt][1] = p; rs0 += p;
            p = __expf(acc_s[nt][2] - mn1); acc_s[nt][2] = p; rs1 += p;
            p = __expf(acc_s[nt][3] - mn1); acc_s[nt][3] = p; rs1 += p;
        }
        rs0 += __shfl_xor_sync(0xffffffffu, rs0, 1);
        rs0 += __shfl_xor_sync(0xffffffffu, rs0, 2);
        rs1 += __shfl_xor_sync(0xffffffffu, rs1, 1);
        rs1 += __shfl_xor_sync(0xffffffffu, rs1, 2);
        li0 = li0 * c0 + rs0;  li1 = li1 * c1 + rs1;
        mi0 = mn0;  mi1 = mn1;
        #pragma unroll
        for (int nt = 0; nt < 8; nt++) {
            acc_o[nt][0] *= c0; acc_o[nt][1] *= c0;
            acc_o[nt][2] *= c1; acc_o[nt][3] *= c1;
        }

        // ---- pack P into A-fragments in registers (C-layout == A-layout) ----
        // A frag for k16-step ks: a0=(row cg, k=2ctg),   a1=(row cg+8, k=2ctg),
        //                         a2=(row cg, k=8+2ctg), a3=(row cg+8, k=8+2ctg)
        // n-tile 2ks covers keys [16ks, 16ks+8) and 2ks+1 covers [16ks+8, 16ks+16).
        uint32_t ap[4][4];
        #pragma unroll
        for (int ks = 0; ks < 4; ks++) {
            ap[ks][0] = pack_h2(acc_s[2 * ks][0],     acc_s[2 * ks][1]);
            ap[ks][1] = pack_h2(acc_s[2 * ks][2],     acc_s[2 * ks][3]);
            ap[ks][2] = pack_h2(acc_s[2 * ks + 1][0], acc_s[2 * ks + 1][1]);
            ap[ks][3] = pack_h2(acc_s[2 * ks + 1][2], acc_s[2 * ks + 1][3]);
        }

        // ---- O += P V (P from registers; V via ldmatrix.trans) ----
        #pragma unroll
        for (int ks = 0; ks < 4; ks++) {
            #pragma unroll
            for (int pr = 0; pr < 4; pr++) {
                const uint32_t offv =
                    SWZ128((uint32_t)((ks * 16 + v_row) * 128 + (pr * 16 + v_col) * 2));
                uint32_t r0, r1, r2, r3;
                ldsm_x4_t(r0, r1, r2, r3, Vb + offv);
                uint32_t b0[2] = {r0, r1}, b1[2] = {r2, r3};
                mma16816h(acc_o[2 * pr],     ap[ks], b0);
                mma16816h(acc_o[2 * pr + 1], ap[ks], b1);
            }
        }
        __syncthreads();   // all warps done with this stage's K/V before refill

        if (kt + 3 < KT) {
            load_kv(stage, kt + 3);
            CP_COMMIT();
        }
    }

    // ---- epilogue: normalize, write single fp16 ao ----
    const int b = bh >> 4, hd = bh & 15;
    const float inv0 = 1.0f / li0, inv1 = 1.0f / li1;
    const int r0 = q0 + w * 16 + cg, r1 = r0 + 8;
    const size_t base0 = ((size_t)(b * SS + r0)) * DD + hd * HDIM;
    const size_t base1 = ((size_t)(b * SS + r1)) * DD + hd * HDIM;
    #pragma unroll
    for (int nt = 0; nt < 8; nt++) {
        const int cc = nt * 8 + ctg * 2;
        *(uint32_t*)(g_aof + base0 + cc) =
            pack_h2(acc_o[nt][0] * inv0, acc_o[nt][1] * inv0);
        *(uint32_t*)(g_aof + base1 + cc) =
            pack_h2(acc_o[nt][2] * inv1, acc_o[nt][3] * inv1);
    }
}

// ---------------------------------------------------------------------------
extern "C" void kernel_launch(void* const* d_in, const int* in_sizes, int n_in,
                              void* d_out, int out_size)
{
    const float* x     = (const float*)d_in[0];
    const float* W_qkv = (const float*)d_in[1];
    const float* b_qkv = (const float*)d_in[2];
    const float* W_out = (const float*)d_in[3];
    const float* b_out = (const float*)d_in[4];
    float* out = (float*)d_out;

    const int gemm_smem = 3 * 2 * 16384;           // 98304 (3 stages x 2 tiles)
    const int attn_smem = 16384 + 3 * 16384;       // 65536 (Q + 3 KV stages)
    cudaFuncSetAttribute(mma_gemm<true>,
                         cudaFuncAttributeMaxDynamicSharedMemorySize, gemm_smem);
    cudaFuncSetAttribute(mma_gemm<false>,
                         cudaFuncAttributeMaxDynamicSharedMemorySize, gemm_smem);
    cudaFuncSetAttribute(attn_mma_kernel,
                         cudaFuncAttributeMaxDynamicSharedMemorySize, attn_smem);

    __half *xf, *wq, *wo, *aof;
    cudaGetSymbolAddress((void**)&xf,  g_xf);
    cudaGetSymbolAddress((void**)&wq,  g_wqkvf);
    cudaGetSymbolAddress((void**)&wo,  g_woutf);
    cudaGetSymbolAddress((void**)&aof, g_aof);

    // 0) prep: convert x to fp16, transpose weights to fp16 [N][K]
    conv_f16_kernel<<<(M_TOT * DD / 4) / 256, 256>>>(
        (const float4*)x, (uint2*)xf);
    transpose_f16_kernel<<<dim3(N_QKV / 32, DD / 32), 256>>>(W_qkv, wq, N_QKV);
    transpose_f16_kernel<<<dim3(DD / 32, DD / 32), 256>>>(W_out, wo, DD);

    // 1) QKV projection (single-product fp16) -> fp16 Q(pre-scaled),K,V
    mma_gemm<true><<<dim3(N_QKV / 128, M_TOT / 128), 256, gemm_smem>>>(
        xf, wq, b_qkv, nullptr);

    // 2) flash attention (fp16 mma.sync, register-resident P) -> fp16 ao
    attn_mma_kernel<<<dim3(SS / 128, BB * HH), 256, attn_smem>>>();

    // 3) output projection (single-product fp16, fp32 out)
    mma_gemm<false><<<dim3(DD / 128, M_TOT / 128), 256, gemm_smem>>>(
        aof, wo, b_out, out);
}